// round 12
// baseline (speedup 1.0000x reference)
#include <cuda_runtime.h>
#include <cuda_fp16.h>
#include <math.h>
#include <stdint.h>

#define NB    2
#define NC    128
#define NH    512
#define NW    512
#define NWIN  4096
#define NWF   1228
#define NSEL  (NB*NWF)
#define SCALE 0.08838834764831845f

// ---------------- static device scratch -------------------------------------
__device__ float g_score[NB*NWIN];
__device__ int   g_sel[NB*NWF];
__device__ int   g_cnt[NB];
__device__ unsigned char g_flag[NB*NWIN];
__device__ float g_gx[NB*NC*64];
__device__ __align__(16) uint2  g_wfrag[6*4096];        // fragment-major weights
__device__ __align__(16) __half g_k16[NB*64*128];       // cross-attn K row-major
__device__ __align__(16) __half g_v1t[NB*128*64];       // cross-attn V transposed

#define MAT_QG 0
#define MAT_LIN 1
#define MAT_Q2 2
#define MAT_K2 3
#define MAT_V2 4
#define MAT_PR 5

// ---------------- helpers ----------------------------------------------------
__device__ __forceinline__ uint32_t h2u(float a, float b) {
    __half2 h = __floats2half2_rn(a, b);
    return reinterpret_cast<uint32_t&>(h);
}
__device__ __forceinline__ void mma16(float* c, uint32_t a0, uint32_t a1,
                                      uint32_t a2, uint32_t a3,
                                      uint32_t b0, uint32_t b1) {
    asm volatile("mma.sync.aligned.m16n8k16.row.col.f32.f16.f16.f32 "
                 "{%0,%1,%2,%3}, {%4,%5,%6,%7}, {%8,%9}, {%0,%1,%2,%3};"
                 : "+f"(c[0]), "+f"(c[1]), "+f"(c[2]), "+f"(c[3])
                 : "r"(a0), "r"(a1), "r"(a2), "r"(a3), "r"(b0), "r"(b1));
}
#define LDSM4(r0, r1, r2, r3, addr) \
    asm volatile("ldmatrix.sync.aligned.m8n8.x4.shared.b16 {%0,%1,%2,%3}, [%4];" \
                 : "=r"(r0), "=r"(r1), "=r"(r2), "=r"(r3) : "r"(addr))
__device__ __forceinline__ uint32_t smem_u32(const void* p) {
    uint32_t a;
    asm("{ .reg .u64 t; cvta.to.shared.u64 t, %1; cvt.u32.u64 %0, t; }" : "=r"(a) : "l"(p));
    return a;
}
// fast GELU: 0.5x(1+tanh(0.79788456x + 0.03567741x^3)) with HW tanh
__device__ __forceinline__ float gelu_fast(float x) {
    float u = fmaf(0.0356774081f * x, x * x, 0.7978845608f * x);
    float th;
    asm("tanh.approx.f32 %0, %1;" : "=f"(th) : "f"(u));
    return 0.5f * x * (1.0f + th);
}

// ---------------- prep kernels ----------------------------------------------
__global__ void wprep_kernel(const float* __restrict__ qgw, const float* __restrict__ lw,
                             const float* __restrict__ qkvw, const float* __restrict__ pw) {
    int i = blockIdx.x * 256 + threadIdx.x;          // 24576
    int mat = i >> 12, r = i & 4095;
    int kb = r >> 9, n8 = (r >> 5) & 15, lane = r & 31;
    int g = lane >> 2, t = lane & 3;
    int n = n8*8 + g, k = kb*16 + 2*t;
    const float* W = (mat == 0) ? qgw : (mat == 1) ? lw
                   : (mat <= 4) ? qkvw + (mat - 2)*16384 : pw;
    const float* row = W + n*128;
    uint2 o;
    o.x = h2u(row[k],   row[k+1]);
    o.y = h2u(row[k+8], row[k+9]);
    g_wfrag[i] = o;
}

// merged: blocks [0,512) compute window scores; blocks [512, 2560) do 8x8 pool
__global__ void scores_pool_kernel(const float* __restrict__ unc,
                                   const float4* __restrict__ fm4) {
    __shared__ float sp[512];
    int t = threadIdx.x;
    if (blockIdx.x < 512) {
        // ---- scores: 16 warps -> 16 windows per block ----
        if (blockIdx.x == 0 && t < NB) g_cnt[t] = 0;
        int gw = blockIdx.x * 16 + (t >> 5);
        int lane = t & 31;
        if (lane == 0) g_flag[gw] = 0;
        int b = gw / NWIN, w = gw % NWIN;
        int wh = w >> 6, ww = w & 63;
        const float* base = unc + ((size_t)b*NH + wh*8)*NW + ww*8;
        int r0 = lane >> 3, c0 = lane & 7;
        double s = (double)base[r0*NW + c0] + (double)base[(r0+4)*NW + c0];
        #pragma unroll
        for (int o = 16; o; o >>= 1) s += __shfl_down_sync(0xffffffffu, s, o);
        if (lane == 0) g_score[gw] = (float)(s * (1.0/64.0));
        return;
    }
    // ---- pool: read-only float4 ----
    int bci = blockIdx.x - 512, ci = bci & 7, bc = bci >> 3;
    const float4* base = fm4 + ((size_t)bc*NH + ci*64)*(NW/4);
    float acc = 0.f;
    #pragma unroll 4
    for (int it = 0; it < 16; it++) {
        float4 v = base[it*512 + t];
        acc += (v.x + v.y) + (v.z + v.w);
    }
    int cell = (t & 127) >> 4;
    int sub  = (t >> 7) * 16 + (t & 15);
    sp[cell*64 + sub] = acc;
    __syncthreads();
    int grp = t >> 6, i = t & 63;
    for (int off = 32; off >= 1; off >>= 1) {
        if (i < off) sp[grp*64 + i] += sp[grp*64 + i + off];
        __syncthreads();
    }
    if (i == 0) g_gx[bc*64 + ci*8 + grp] = sp[grp*64] * (1.0f/4096.0f);
}

__global__ void select_kernel() {
    __shared__ float s_sc[NWIN];
    int b = blockIdx.x >> 2, part = blockIdx.x & 3;
    const float* sc = g_score + b*NWIN;
    for (int i = threadIdx.x; i < NWIN; i += 1024) s_sc[i] = sc[i];
    __syncthreads();
    int w = part*1024 + threadIdx.x;
    float my = s_sc[w];
    int rank = 0;
    #pragma unroll 8
    for (int j = 0; j < NWIN; j++) {
        float v = s_sc[j];
        rank += (v > my) || (v == my && j < w);
    }
    if (rank < NWF) {
        int pos = atomicAdd(&g_cnt[b], 1);
        g_sel[b*NWF + pos] = w;
        g_flag[b*NWIN + w] = 1;
    }
}

// k1, v1 for cross attention: 16 blocks, g staged in smem once
__global__ void kv_kernel(const float* __restrict__ kvw) {
    __shared__ float sg[128][65];
    int b = blockIdx.x >> 3, grp = blockIdx.x & 7;
    int tid = threadIdx.x;
    for (int i = tid; i < 8192; i += 256) sg[i >> 6][i & 63] = g_gx[b*8192 + i];
    __syncthreads();
    int p = tid & 63, q4 = tid >> 6;
    #pragma unroll
    for (int u = 0; u < 8; u++) {
        int co = grp*32 + q4*8 + u;        // 0..255 (0..127 = k, 128..255 = v)
        const float* wr = kvw + (size_t)co * 128;
        float a = 0.f;
        #pragma unroll 8
        for (int cc = 0; cc < 128; cc++) a = fmaf(sg[cc][p], __ldg(&wr[cc]), a);
        if (co < 128) g_k16[(b*64 + p)*128 + co]         = __float2half(a);
        else          g_v1t[(b*128 + (co - 128))*64 + p] = __float2half(a);
    }
}

// ---------------- fused window kernel (+ distributed copy) -------------------
#define AST 136    // half stride (s_a, s_b)
#define VST 72     // half stride (s_vt)
#define WST 132    // float stride (s_wf)
#define PST 68     // float stride (s_p)
#define OFF_WF 0
#define OFF_P  33792
#define OFF_A  51200
#define OFF_B  68608
#define OFF_VT 86016
#define SMEMB  104448

// C[4][2][4] = A(64x128 @ ua) @ W^T via fragment-major weights
__device__ __forceinline__ void gemmW(uint32_t ua, const uint2* __restrict__ wfr,
                                      int lane, int wp, float C[4][2][4]) {
    #pragma unroll
    for (int mt = 0; mt < 4; mt++)
        #pragma unroll
        for (int nt = 0; nt < 2; nt++)
            #pragma unroll
            for (int k = 0; k < 4; k++) C[mt][nt][k] = 0.f;
    uint32_t ab = ua + (((lane & 15)*AST + ((lane & 16) >> 1)) << 1);
    #pragma unroll
    for (int kb = 0; kb < 8; kb++) {
        uint2 w0 = __ldg(&wfr[(kb*16 + 2*wp    )*32 + lane]);
        uint2 w1 = __ldg(&wfr[(kb*16 + 2*wp + 1)*32 + lane]);
        #pragma unroll
        for (int mt = 0; mt < 4; mt++) {
            uint32_t a0, a1, a2, a3;
            LDSM4(a0, a1, a2, a3, ab + mt*(AST*32) + kb*32);
            mma16(C[mt][0], a0, a1, a2, a3, w0.x, w0.y);
            mma16(C[mt][1], a0, a1, a2, a3, w1.x, w1.y);
        }
    }
}

// Cq[4][4] = Q(ua) @ K(ub)^T, warp strip of 8 cols
__device__ __forceinline__ void gemmQK(uint32_t ua, uint32_t ub,
                                       int lane, int wp, float Cq[4][4]) {
    #pragma unroll
    for (int mt = 0; mt < 4; mt++)
        #pragma unroll
        for (int k = 0; k < 4; k++) Cq[mt][k] = 0.f;
    uint32_t ab = ua + (((lane & 15)*AST + ((lane & 16) >> 1)) << 1);
    uint32_t bb = ub + (((wp*8 + (lane & 7))*AST + (lane >> 3)*8) << 1);
    #pragma unroll
    for (int kp = 0; kp < 4; kp++) {
        uint32_t b0, b1, b2, b3;
        LDSM4(b0, b1, b2, b3, bb + kp*64);
        #pragma unroll
        for (int mt = 0; mt < 4; mt++) {
            uint32_t a0, a1, a2, a3;
            LDSM4(a0, a1, a2, a3, ab + mt*(AST*32) + kp*64);
            mma16(Cq[mt], a0, a1, a2, a3, b0, b1);
            LDSM4(a0, a1, a2, a3, ab + mt*(AST*32) + kp*64 + 32);
            mma16(Cq[mt], a0, a1, a2, a3, b2, b3);
        }
    }
}

// C[4][2][4] = attn(ua cols 0..63) @ V(uvt transposed), K=64
__device__ __forceinline__ void gemmAV(uint32_t ua, uint32_t uvt,
                                       int lane, int wp, float C[4][2][4]) {
    #pragma unroll
    for (int mt = 0; mt < 4; mt++)
        #pragma unroll
        for (int nt = 0; nt < 2; nt++)
            #pragma unroll
            for (int k = 0; k < 4; k++) C[mt][nt][k] = 0.f;
    uint32_t ab = ua + (((lane & 15)*AST + ((lane & 16) >> 1)) << 1);
    uint32_t vb = uvt + (((wp*16 + (lane & 7) + ((lane & 16) >> 1))*VST + (lane & 8)) << 1);
    #pragma unroll
    for (int kb = 0; kb < 4; kb++) {
        uint32_t b0, b1, b2, b3;
        LDSM4(b0, b1, b2, b3, vb + kb*32);
        #pragma unroll
        for (int mt = 0; mt < 4; mt++) {
            uint32_t a0, a1, a2, a3;
            LDSM4(a0, a1, a2, a3, ab + mt*(AST*32) + kb*32);
            mma16(C[mt][0], a0, a1, a2, a3, b0, b1);
            mma16(C[mt][1], a0, a1, a2, a3, b2, b3);
        }
    }
}

__global__ void __launch_bounds__(256, 2) window_kernel(
    const float* __restrict__ fm,
    const float* __restrict__ lb, const float* __restrict__ pb,
    float* __restrict__ out)
{
    extern __shared__ char sm[];
    float*  s_wf = (float*) (sm + OFF_WF);
    float*  s_p  = (float*) (sm + OFF_P);
    __half* s_a  = (__half*)(sm + OFF_A);
    __half* s_b  = (__half*)(sm + OFF_B);
    __half* s_vt = (__half*)(sm + OFF_VT);
    uint32_t ua  = smem_u32(s_a);
    uint32_t ub  = smem_u32(s_b);
    uint32_t uvt = smem_u32(s_vt);

    int tid = threadIdx.x, wp = tid >> 5, lane = tid & 31;
    int g = lane >> 2, t = lane & 3;
    int idx = blockIdx.x;
    int b = idx / NWF;
    int w = g_sel[idx];
    int wh = w >> 6, ww = w & 63;
    const size_t plane = (size_t)NH * NW;
    const float* fbase = fm  + (size_t)b*NC*plane + (size_t)(wh*8)*NW + ww*8;
    float*       obase = out + (size_t)b*NC*plane + (size_t)(wh*8)*NW + ww*8;

    // ---- distributed copy of non-selected pixels (54-row slab per block) ----
    {
        const float4* fm4 = (const float4*)fm;
        float4* out4 = (float4*)out;
        int rstart = idx * 54;
        #pragma unroll 1
        for (int u = 0; u < 27; u++) {
            int li = u*256 + tid;
            int row = rstart + (li >> 7), j = li & 127;
            if (row < NB*NC*NH) {
                int bb = row >> 16;            // 65536 rows per batch
                int h  = row & 511;
                if (!g_flag[bb*NWIN + (h >> 3)*64 + (j >> 1)])
                    out4[(size_t)row*128 + j] = fm4[(size_t)row*128 + j];
            }
        }
    }

    // gather window (fp32 master + fp16 mirror) + stage k1 / v1t
    {
        int col = tid & 7, r = (tid >> 3) & 7, c0 = tid >> 6;
        int t8 = r*8 + col;
        #pragma unroll
        for (int k = 0; k < 32; k++) {
            int c = c0 + 4*k;
            float v = fbase[(size_t)c*plane + r*NW + col];
            s_wf[t8*WST + c] = v;
            s_a[t8*AST + c] = __float2half(v);
        }
        const uint4* kg = (const uint4*)(g_k16 + b*8192);
        const uint4* vg = (const uint4*)(g_v1t + b*8192);
        for (int i = tid; i < 1024; i += 256) {
            int row = i >> 4, c16 = i & 15;
            *(uint4*)(s_b + row*AST + c16*8) = kg[row*16 + c16];
        }
        for (int i = tid; i < 1024; i += 256) {
            int row = i >> 3, c8 = i & 7;
            *(uint4*)(s_vt + row*VST + c8*8) = vg[row*8 + c8];
        }
    }
    __syncthreads();

    float C[4][2][4];
    float Cq[4][4];

    #define FOR_FRAG for (int mt = 0; mt < 4; mt++) for (int nt = 0; nt < 2; nt++)
    #define R0 (mt*16 + g)
    #define R1 (mt*16 + g + 8)
    #define CL (wp*16 + nt*8 + 2*t)

    // ---- q1 = wf @ Wqg^T ----
    gemmW(ua, g_wfrag + MAT_QG*4096, lane, wp, C);
    __syncthreads();
    FOR_FRAG {
        *(uint32_t*)(s_a + R0*AST + CL) = h2u(C[mt][nt][0], C[mt][nt][1]);
        *(uint32_t*)(s_a + R1*AST + CL) = h2u(C[mt][nt][2], C[mt][nt][3]);
    }
    __syncthreads();

    // ---- logits1 = q1 @ k1^T ----
    gemmQK(ua, ub, lane, wp, Cq);
    #pragma unroll
    for (int mt = 0; mt < 4; mt++) {
        int cc = wp*8 + 2*t;
        s_p[(mt*16+g)*PST + cc]     = Cq[mt][0]*SCALE;
        s_p[(mt*16+g)*PST + cc+1]   = Cq[mt][1]*SCALE;
        s_p[(mt*16+g+8)*PST + cc]   = Cq[mt][2]*SCALE;
        s_p[(mt*16+g+8)*PST + cc+1] = Cq[mt][3]*SCALE;
    }
    __syncthreads();

    // ---- softmax1 -> s_a cols 0..63 (half) ----
    {
        int row = tid >> 2, q = tid & 3;
        float* pr = s_p + row*PST + q*16;
        float m = -1e30f, v[16];
        #pragma unroll
        for (int k = 0; k < 16; k++) { v[k] = pr[k]; m = fmaxf(m, v[k]); }
        m = fmaxf(m, __shfl_xor_sync(0xffffffffu, m, 1));
        m = fmaxf(m, __shfl_xor_sync(0xffffffffu, m, 2));
        float s = 0.f;
        #pragma unroll
        for (int k = 0; k < 16; k++) { v[k] = __expf(v[k] - m); s += v[k]; }
        s += __shfl_xor_sync(0xffffffffu, s, 1);
        s += __shfl_xor_sync(0xffffffffu, s, 2);
        float inv = 1.0f / s;
        #pragma unroll
        for (int u = 0; u < 8; u++)
            *(uint32_t*)(s_a + row*AST + q*16 + 2*u) = h2u(v[2*u]*inv, v[2*u+1]*inv);
    }
    __syncthreads();

    // ---- av1 = attn @ v1 ; wf += av1 ----
    gemmAV(ua, uvt, lane, wp, C);
    __syncthreads();
    FOR_FRAG {
        float f0 = s_wf[R0*WST + CL]   + C[mt][nt][0];
        float f1 = s_wf[R0*WST + CL+1] + C[mt][nt][1];
        float f2 = s_wf[R1*WST + CL]   + C[mt][nt][2];
        float f3 = s_wf[R1*WST + CL+1] + C[mt][nt][3];
        s_wf[R0*WST + CL] = f0; s_wf[R0*WST + CL+1] = f1;
        s_wf[R1*WST + CL] = f2; s_wf[R1*WST + CL+1] = f3;
        *(uint32_t*)(s_a + R0*AST + CL) = h2u(f0, f1);
        *(uint32_t*)(s_a + R1*AST + CL) = h2u(f2, f3);
    }
    __syncthreads();

    // ---- MLP1: wf += gelu(wf @ lw^T + lb) ----
    gemmW(ua, g_wfrag + MAT_LIN*4096, lane, wp, C);
    __syncthreads();
    FOR_FRAG {
        float b0 = __ldg(&lb[CL]), b1 = __ldg(&lb[CL+1]);
        float f0 = s_wf[R0*WST + CL]   + gelu_fast(C[mt][nt][0] + b0);
        float f1 = s_wf[R0*WST + CL+1] + gelu_fast(C[mt][nt][1] + b1);
        float f2 = s_wf[R1*WST + CL]   + gelu_fast(C[mt][nt][2] + b0);
        float f3 = s_wf[R1*WST + CL+1] + gelu_fast(C[mt][nt][3] + b1);
        s_wf[R0*WST + CL] = f0; s_wf[R0*WST + CL+1] = f1;
        s_wf[R1*WST + CL] = f2; s_wf[R1*WST + CL+1] = f3;
        *(uint32_t*)(s_a + R0*AST + CL) = h2u(f0, f1);
        *(uint32_t*)(s_a + R1*AST + CL) = h2u(f2, f3);
    }
    __syncthreads();

    // ---- self-attention projections ----
    gemmW(ua, g_wfrag + MAT_K2*4096, lane, wp, C);
    FOR_FRAG {
        *(uint32_t*)(s_b + R0*AST + CL) = h2u(C[mt][nt][0], C[mt][nt][1]);
        *(uint32_t*)(s_b + R1*AST + CL) = h2u(C[mt][nt][2], C[mt][nt][3]);
    }
    gemmW(ua, g_wfrag + MAT_V2*4096, lane, wp, C);
    FOR_FRAG {
        s_vt[(CL  )*VST + R0] = __float2half(C[mt][nt][0]);
        s_vt[(CL+1)*VST + R0] = __float2half(C[mt][nt][1]);
        s_vt[(CL  )*VST + R1] = __float2half(C[mt][nt][2]);
        s_vt[(CL+1)*VST + R1] = __float2half(C[mt][nt][3]);
    }
    gemmW(ua, g_wfrag + MAT_Q2*4096, lane, wp, C);
    __syncthreads();
    FOR_FRAG {
        *(uint32_t*)(s_a + R0*AST + CL) = h2u(C[mt][nt][0], C[mt][nt][1]);
        *(uint32_t*)(s_a + R1*AST + CL) = h2u(C[mt][nt][2], C[mt][nt][3]);
    }
    __syncthreads();

    // ---- logits2 = q2 @ k2^T ----
    gemmQK(ua, ub, lane, wp, Cq);
    #pragma unroll
    for (int mt = 0; mt < 4; mt++) {
        int cc = wp*8 + 2*t;
        s_p[(mt*16+g)*PST + cc]     = Cq[mt][0]*SCALE;
        s_p[(mt*16+g)*PST + cc+1]   = Cq[mt][1]*SCALE;
        s_p[(mt*16+g+8)*PST + cc]   = Cq[mt][2]*SCALE;
        s_p[(mt*16+g+8)*PST + cc+1] = Cq[mt][3]*SCALE;
    }
    __syncthreads();
    {
        int row = tid >> 2, q = tid & 3;
        float* pr = s_p + row*PST + q*16;
        float m = -1e30f, v[16];
        #pragma unroll
        for (int k = 0; k < 16; k++) { v[k] = pr[k]; m = fmaxf(m, v[k]); }
        m = fmaxf(m, __shfl_xor_sync(0xffffffffu, m, 1));
        m = fmaxf(m, __shfl_xor_sync(0xffffffffu, m, 2));
        float s = 0.f;
        #pragma unroll
        for (int k = 0; k < 16; k++) { v[k] = __expf(v[k] - m); s += v[k]; }
        s += __shfl_xor_sync(0xffffffffu, s, 1);
        s += __shfl_xor_sync(0xffffffffu, s, 2);
        float inv = 1.0f / s;
        #pragma unroll
        for (int u = 0; u < 8; u++)
            *(uint32_t*)(s_a + row*AST + q*16 + 2*u) = h2u(v[2*u]*inv, v[2*u+1]*inv);
    }
    __syncthreads();

    // ---- av2 = attn @ v2 -> s_b (half) ----
    gemmAV(ua, uvt, lane, wp, C);
    FOR_FRAG {
        *(uint32_t*)(s_b + R0*AST + CL) = h2u(C[mt][nt][0], C[mt][nt][1]);
        *(uint32_t*)(s_b + R1*AST + CL) = h2u(C[mt][nt][2], C[mt][nt][3]);
    }
    __syncthreads();

    // ---- scrambled residual: wf[i][j] += av[j%64][2i + j/64] ----
    #pragma unroll
    for (int k = 0; k < 32; k++) {
        int id2 = tid + 256*k;
        int i = id2 >> 7, j = id2 & 127;
        float f = s_wf[i*WST + j] + __half2float(s_b[(j & 63)*AST + 2*i + (j >> 6)]);
        s_wf[i*WST + j] = f;
        s_a[i*AST + j] = __float2half(f);
    }
    __syncthreads();

    // ---- MLP2: wf += gelu(wf @ pw^T + pb) ----
    gemmW(ua, g_wfrag + MAT_PR*4096, lane, wp, C);
    __syncthreads();
    FOR_FRAG {
        float b0 = __ldg(&pb[CL]), b1 = __ldg(&pb[CL+1]);
        s_wf[R0*WST + CL]   += gelu_fast(C[mt][nt][0] + b0);
        s_wf[R0*WST + CL+1] += gelu_fast(C[mt][nt][1] + b1);
        s_wf[R1*WST + CL]   += gelu_fast(C[mt][nt][2] + b0);
        s_wf[R1*WST + CL+1] += gelu_fast(C[mt][nt][3] + b1);
    }
    __syncthreads();

    // ---- scatter ----
    {
        int col = tid & 7, r = (tid >> 3) & 7, c0 = tid >> 6;
        int t8 = r*8 + col;
        #pragma unroll
        for (int k = 0; k < 32; k++) {
            int c = c0 + 4*k;
            obase[(size_t)c*plane + r*NW + col] = s_wf[t8*WST + c];
        }
    }
    #undef FOR_FRAG
    #undef R0
    #undef R1
    #undef CL
}

// ---------------- launch ------------------------------------------------------
extern "C" void kernel_launch(void* const* d_in, const int* in_sizes, int n_in,
                              void* d_out, int out_size) {
    const float* fm   = (const float*)d_in[0];
    const float* unc  = (const float*)d_in[1];
    const float* qgw  = (const float*)d_in[2];
    const float* kvw  = (const float*)d_in[3];
    const float* lw   = (const float*)d_in[4];
    const float* lb   = (const float*)d_in[5];
    const float* qkvw = (const float*)d_in[6];
    const float* pw   = (const float*)d_in[7];
    const float* pb   = (const float*)d_in[8];
    float* out = (float*)d_out;

    cudaFuncSetAttribute(window_kernel,
                         cudaFuncAttributeMaxDynamicSharedMemorySize, SMEMB);

    wprep_kernel<<<96, 256>>>(qgw, lw, qkvw, pw);
    scores_pool_kernel<<<2560, 512>>>(unc, (const float4*)fm);
    select_kernel<<<8, 1024>>>();
    kv_kernel<<<16, 256>>>(kvw);
    window_kernel<<<NSEL, 256, SMEMB>>>(fm, lb, pb, out);
}

// round 14
// speedup vs baseline: 1.2279x; 1.2279x over previous
#include <cuda_runtime.h>
#include <cuda_fp16.h>
#include <math.h>
#include <stdint.h>

#define NB    2
#define NC    128
#define NH    512
#define NW    512
#define NWIN  4096
#define NWF   1228
#define NSEL  (NB*NWF)
#define SCALE 0.08838834764831845f

// ---------------- static device scratch -------------------------------------
__device__ float g_score[NB*NWIN];
__device__ int   g_sel[NB*NWF];
__device__ int   g_cnt[NB];
__device__ float g_gx[NB*NC*64];
__device__ __align__(16) uint2  g_wfrag[6*4096];        // fragment-major weights
__device__ __align__(16) __half g_k16[NB*64*128];       // cross-attn K row-major
__device__ __align__(16) __half g_v1t[NB*128*64];       // cross-attn V transposed

#define MAT_QG 0
#define MAT_LIN 1
#define MAT_Q2 2
#define MAT_K2 3
#define MAT_V2 4
#define MAT_PR 5

// ---------------- helpers ----------------------------------------------------
__device__ __forceinline__ uint32_t h2u(float a, float b) {
    __half2 h = __floats2half2_rn(a, b);
    return reinterpret_cast<uint32_t&>(h);
}
__device__ __forceinline__ void mma16(float* c, uint32_t a0, uint32_t a1,
                                      uint32_t a2, uint32_t a3,
                                      uint32_t b0, uint32_t b1) {
    asm volatile("mma.sync.aligned.m16n8k16.row.col.f32.f16.f16.f32 "
                 "{%0,%1,%2,%3}, {%4,%5,%6,%7}, {%8,%9}, {%0,%1,%2,%3};"
                 : "+f"(c[0]), "+f"(c[1]), "+f"(c[2]), "+f"(c[3])
                 : "r"(a0), "r"(a1), "r"(a2), "r"(a3), "r"(b0), "r"(b1));
}
#define LDSM4(r0, r1, r2, r3, addr) \
    asm volatile("ldmatrix.sync.aligned.m8n8.x4.shared.b16 {%0,%1,%2,%3}, [%4];" \
                 : "=r"(r0), "=r"(r1), "=r"(r2), "=r"(r3) : "r"(addr))
__device__ __forceinline__ uint32_t smem_u32(const void* p) {
    uint32_t a;
    asm("{ .reg .u64 t; cvta.to.shared.u64 t, %1; cvt.u32.u64 %0, t; }" : "=r"(a) : "l"(p));
    return a;
}
// fast GELU with HW tanh
__device__ __forceinline__ float gelu_fast(float x) {
    float u = fmaf(0.0356774081f * x, x * x, 0.7978845608f * x);
    float th;
    asm("tanh.approx.f32 %0, %1;" : "=f"(th) : "f"(u));
    return 0.5f * x * (1.0f + th);
}

// ---------------- merged prep kernel -----------------------------------------
// blocks [0,2048): copy-all + 8x8 pool ; [2048,2560): scores ; [2560,2608): wprep
__global__ void prep_kernel(const float4* __restrict__ fm4, float4* __restrict__ out4,
                            const float* __restrict__ unc,
                            const float* __restrict__ qgw, const float* __restrict__ lw,
                            const float* __restrict__ qkvw, const float* __restrict__ pw) {
    int t = threadIdx.x;
    int bid = blockIdx.x;
    if (bid < 2048) {
        // ---- copy + pool ----
        __shared__ float sp[512];
        int ci = bid & 7, bc = bid >> 3;
        const float4* base = fm4  + ((size_t)bc*NH + ci*64)*(NW/4);
        float4*       ob   = out4 + ((size_t)bc*NH + ci*64)*(NW/4);
        float acc = 0.f;
        #pragma unroll 4
        for (int it = 0; it < 16; it++) {
            int i4 = it*512 + t;
            float4 v = base[i4];
            ob[i4] = v;
            acc += (v.x + v.y) + (v.z + v.w);
        }
        int cell = (t & 127) >> 4;
        int sub  = (t >> 7) * 16 + (t & 15);
        sp[cell*64 + sub] = acc;
        __syncthreads();
        int grp = t >> 6, i = t & 63;
        for (int off = 32; off >= 1; off >>= 1) {
            if (i < off) sp[grp*64 + i] += sp[grp*64 + i + off];
            __syncthreads();
        }
        if (i == 0) g_gx[bc*64 + ci*8 + grp] = sp[grp*64] * (1.0f/4096.0f);
        return;
    }
    if (bid < 2560) {
        // ---- window scores (16 warps = 16 windows per block) ----
        int sb = bid - 2048;
        if (sb == 0 && t < NB) g_cnt[t] = 0;
        int gw = sb * 16 + (t >> 5);
        int lane = t & 31;
        int b = gw / NWIN, w = gw % NWIN;
        int wh = w >> 6, ww = w & 63;
        const float* base = unc + ((size_t)b*NH + wh*8)*NW + ww*8;
        int r0 = lane >> 3, c0 = lane & 7;
        double s = (double)base[r0*NW + c0] + (double)base[(r0+4)*NW + c0];
        #pragma unroll
        for (int o = 16; o; o >>= 1) s += __shfl_down_sync(0xffffffffu, s, o);
        if (lane == 0) g_score[gw] = (float)(s * (1.0/64.0));
        return;
    }
    // ---- weight prep: fragment-major fp16 ----
    int i = (bid - 2560) * 512 + t;                 // < 24576
    if (i >= 24576) return;
    int mat = i >> 12, r = i & 4095;
    int kb = r >> 9, n8 = (r >> 5) & 15, lane = r & 31;
    int g = lane >> 2, tt = lane & 3;
    int n = n8*8 + g, k = kb*16 + 2*tt;
    const float* W = (mat == 0) ? qgw : (mat == 1) ? lw
                   : (mat <= 4) ? qkvw + (mat - 2)*16384 : pw;
    const float* row = W + n*128;
    uint2 o;
    o.x = h2u(row[k],   row[k+1]);
    o.y = h2u(row[k+8], row[k+9]);
    g_wfrag[i] = o;
}

// ---------------- merged select + kv kernel ----------------------------------
// blocks [0,8): stable top-k select ; blocks [8,16): k1/v1 projection
// smem sized for the LARGER user: kv path needs [128][65] floats = 33280 B.
__global__ void selkv_kernel(const float* __restrict__ kvw) {
    __shared__ float smem_buf[128*65];
    int tid = threadIdx.x;
    if (blockIdx.x < 8) {
        float* s_sc = smem_buf;                     // uses first NWIN floats
        int b = blockIdx.x >> 2, part = blockIdx.x & 3;
        const float* sc = g_score + b*NWIN;
        for (int i = tid; i < NWIN; i += 1024) s_sc[i] = sc[i];
        __syncthreads();
        int w = part*1024 + tid;
        float my = s_sc[w];
        int rank = 0;
        #pragma unroll 8
        for (int j = 0; j < NWIN; j++) {
            float v = s_sc[j];
            rank += (v > my) || (v == my && j < w);
        }
        if (rank < NWF) {
            int pos = atomicAdd(&g_cnt[b], 1);
            g_sel[b*NWF + pos] = w;
        }
        return;
    }
    // ---- kv: 8 blocks x 1024 threads, 4 dot-products per thread ----
    int k = blockIdx.x - 8;              // 0..7
    int b = k >> 2, rgrp = k & 3;        // rgrp covers out-rows [rgrp*64, +64)
    float (*sg)[65] = (float (*)[65])smem_buf;
    for (int i = tid; i < 8192; i += 1024) sg[i >> 6][i & 63] = g_gx[b*8192 + i];
    __syncthreads();
    int p = tid & 63, rsub = tid >> 6;   // rsub 0..15
    #pragma unroll
    for (int u = 0; u < 4; u++) {
        int co = rgrp*64 + rsub*4 + u;   // 0..255 (0..127 = k, 128..255 = v)
        const float* wr = kvw + (size_t)co * 128;
        float a = 0.f;
        #pragma unroll 8
        for (int cc = 0; cc < 128; cc++) a = fmaf(sg[cc][p], __ldg(&wr[cc]), a);
        if (co < 128) g_k16[(b*64 + p)*128 + co]         = __float2half(a);
        else          g_v1t[(b*128 + (co - 128))*64 + p] = __float2half(a);
    }
}

// ---------------- fused window kernel ----------------------------------------
#define AST 136    // half stride (s_a, s_b)
#define VST 72     // half stride (s_vt)
#define WST 132    // float stride (s_wf)
#define PST 68     // float stride (s_p)
#define OFF_WF 0
#define OFF_P  33792
#define OFF_A  51200
#define OFF_B  68608
#define OFF_VT 86016
#define SMEMB  104448

// C[4][2][4] = A(64x128 @ ua) @ W^T via fragment-major weights
__device__ __forceinline__ void gemmW(uint32_t ua, const uint2* __restrict__ wfr,
                                      int lane, int wp, float C[4][2][4]) {
    #pragma unroll
    for (int mt = 0; mt < 4; mt++)
        #pragma unroll
        for (int nt = 0; nt < 2; nt++)
            #pragma unroll
            for (int k = 0; k < 4; k++) C[mt][nt][k] = 0.f;
    uint32_t ab = ua + (((lane & 15)*AST + ((lane & 16) >> 1)) << 1);
    #pragma unroll
    for (int kb = 0; kb < 8; kb++) {
        uint2 w0 = __ldg(&wfr[(kb*16 + 2*wp    )*32 + lane]);
        uint2 w1 = __ldg(&wfr[(kb*16 + 2*wp + 1)*32 + lane]);
        #pragma unroll
        for (int mt = 0; mt < 4; mt++) {
            uint32_t a0, a1, a2, a3;
            LDSM4(a0, a1, a2, a3, ab + mt*(AST*32) + kb*32);
            mma16(C[mt][0], a0, a1, a2, a3, w0.x, w0.y);
            mma16(C[mt][1], a0, a1, a2, a3, w1.x, w1.y);
        }
    }
}

// Cq[4][4] = Q(ua) @ K(ub)^T, warp strip of 8 cols
__device__ __forceinline__ void gemmQK(uint32_t ua, uint32_t ub,
                                       int lane, int wp, float Cq[4][4]) {
    #pragma unroll
    for (int mt = 0; mt < 4; mt++)
        #pragma unroll
        for (int k = 0; k < 4; k++) Cq[mt][k] = 0.f;
    uint32_t ab = ua + (((lane & 15)*AST + ((lane & 16) >> 1)) << 1);
    uint32_t bb = ub + (((wp*8 + (lane & 7))*AST + (lane >> 3)*8) << 1);
    #pragma unroll
    for (int kp = 0; kp < 4; kp++) {
        uint32_t b0, b1, b2, b3;
        LDSM4(b0, b1, b2, b3, bb + kp*64);
        #pragma unroll
        for (int mt = 0; mt < 4; mt++) {
            uint32_t a0, a1, a2, a3;
            LDSM4(a0, a1, a2, a3, ab + mt*(AST*32) + kp*64);
            mma16(Cq[mt], a0, a1, a2, a3, b0, b1);
            LDSM4(a0, a1, a2, a3, ab + mt*(AST*32) + kp*64 + 32);
            mma16(Cq[mt], a0, a1, a2, a3, b2, b3);
        }
    }
}

// C[4][2][4] = attn(ua cols 0..63) @ V(uvt transposed), K=64
__device__ __forceinline__ void gemmAV(uint32_t ua, uint32_t uvt,
                                       int lane, int wp, float C[4][2][4]) {
    #pragma unroll
    for (int mt = 0; mt < 4; mt++)
        #pragma unroll
        for (int nt = 0; nt < 2; nt++)
            #pragma unroll
            for (int k = 0; k < 4; k++) C[mt][nt][k] = 0.f;
    uint32_t ab = ua + (((lane & 15)*AST + ((lane & 16) >> 1)) << 1);
    uint32_t vb = uvt + (((wp*16 + (lane & 7) + ((lane & 16) >> 1))*VST + (lane & 8)) << 1);
    #pragma unroll
    for (int kb = 0; kb < 4; kb++) {
        uint32_t b0, b1, b2, b3;
        LDSM4(b0, b1, b2, b3, vb + kb*32);
        #pragma unroll
        for (int mt = 0; mt < 4; mt++) {
            uint32_t a0, a1, a2, a3;
            LDSM4(a0, a1, a2, a3, ab + mt*(AST*32) + kb*32);
            mma16(C[mt][0], a0, a1, a2, a3, b0, b1);
            mma16(C[mt][1], a0, a1, a2, a3, b2, b3);
        }
    }
}

__global__ void __launch_bounds__(256, 2) window_kernel(
    const float* __restrict__ fm,
    const float* __restrict__ lb, const float* __restrict__ pb,
    float* __restrict__ out)
{
    extern __shared__ char sm[];
    float*  s_wf = (float*) (sm + OFF_WF);
    float*  s_p  = (float*) (sm + OFF_P);
    __half* s_a  = (__half*)(sm + OFF_A);
    __half* s_b  = (__half*)(sm + OFF_B);
    __half* s_vt = (__half*)(sm + OFF_VT);
    uint32_t ua  = smem_u32(s_a);
    uint32_t ub  = smem_u32(s_b);
    uint32_t uvt = smem_u32(s_vt);

    int tid = threadIdx.x, wp = tid >> 5, lane = tid & 31;
    int g = lane >> 2, t = lane & 3;
    int idx = blockIdx.x;
    int b = idx / NWF;
    int w = g_sel[idx];
    int wh = w >> 6, ww = w & 63;
    const size_t plane = (size_t)NH * NW;
    const float* fbase = fm  + (size_t)b*NC*plane + (size_t)(wh*8)*NW + ww*8;
    float*       obase = out + (size_t)b*NC*plane + (size_t)(wh*8)*NW + ww*8;

    // gather window (fp32 master + fp16 mirror) + stage k1 / v1t
    {
        int col = tid & 7, r = (tid >> 3) & 7, c0 = tid >> 6;
        int t8 = r*8 + col;
        #pragma unroll
        for (int k = 0; k < 32; k++) {
            int c = c0 + 4*k;
            float v = fbase[(size_t)c*plane + r*NW + col];
            s_wf[t8*WST + c] = v;
            s_a[t8*AST + c] = __float2half(v);
        }
        const uint4* kg = (const uint4*)(g_k16 + b*8192);
        const uint4* vg = (const uint4*)(g_v1t + b*8192);
        for (int i = tid; i < 1024; i += 256) {
            int row = i >> 4, c16 = i & 15;
            *(uint4*)(s_b + row*AST + c16*8) = kg[row*16 + c16];
        }
        for (int i = tid; i < 1024; i += 256) {
            int row = i >> 3, c8 = i & 7;
            *(uint4*)(s_vt + row*VST + c8*8) = vg[row*8 + c8];
        }
    }
    __syncthreads();

    float C[4][2][4];
    float Cq[4][4];

    #define FOR_FRAG for (int mt = 0; mt < 4; mt++) for (int nt = 0; nt < 2; nt++)
    #define R0 (mt*16 + g)
    #define R1 (mt*16 + g + 8)
    #define CL (wp*16 + nt*8 + 2*t)

    // ---- q1 = wf @ Wqg^T ----
    gemmW(ua, g_wfrag + MAT_QG*4096, lane, wp, C);
    __syncthreads();
    FOR_FRAG {
        *(uint32_t*)(s_a + R0*AST + CL) = h2u(C[mt][nt][0], C[mt][nt][1]);
        *(uint32_t*)(s_a + R1*AST + CL) = h2u(C[mt][nt][2], C[mt][nt][3]);
    }
    __syncthreads();

    // ---- logits1 = q1 @ k1^T ----
    gemmQK(ua, ub, lane, wp, Cq);
    #pragma unroll
    for (int mt = 0; mt < 4; mt++) {
        int cc = wp*8 + 2*t;
        s_p[(mt*16+g)*PST + cc]     = Cq[mt][0]*SCALE;
        s_p[(mt*16+g)*PST + cc+1]   = Cq[mt][1]*SCALE;
        s_p[(mt*16+g+8)*PST + cc]   = Cq[mt][2]*SCALE;
        s_p[(mt*16+g+8)*PST + cc+1] = Cq[mt][3]*SCALE;
    }
    __syncthreads();

    // ---- softmax1 -> s_a cols 0..63 (half) ----
    {
        int row = tid >> 2, q = tid & 3;
        float* pr = s_p + row*PST + q*16;
        float m = -1e30f, v[16];
        #pragma unroll
        for (int k = 0; k < 16; k++) { v[k] = pr[k]; m = fmaxf(m, v[k]); }
        m = fmaxf(m, __shfl_xor_sync(0xffffffffu, m, 1));
        m = fmaxf(m, __shfl_xor_sync(0xffffffffu, m, 2));
        float s = 0.f;
        #pragma unroll
        for (int k = 0; k < 16; k++) { v[k] = __expf(v[k] - m); s += v[k]; }
        s += __shfl_xor_sync(0xffffffffu, s, 1);
        s += __shfl_xor_sync(0xffffffffu, s, 2);
        float inv = 1.0f / s;
        #pragma unroll
        for (int u = 0; u < 8; u++)
            *(uint32_t*)(s_a + row*AST + q*16 + 2*u) = h2u(v[2*u]*inv, v[2*u+1]*inv);
    }
    __syncthreads();

    // ---- av1 = attn @ v1 ; wf += av1 ----
    gemmAV(ua, uvt, lane, wp, C);
    __syncthreads();
    FOR_FRAG {
        float f0 = s_wf[R0*WST + CL]   + C[mt][nt][0];
        float f1 = s_wf[R0*WST + CL+1] + C[mt][nt][1];
        float f2 = s_wf[R1*WST + CL]   + C[mt][nt][2];
        float f3 = s_wf[R1*WST + CL+1] + C[mt][nt][3];
        s_wf[R0*WST + CL] = f0; s_wf[R0*WST + CL+1] = f1;
        s_wf[R1*WST + CL] = f2; s_wf[R1*WST + CL+1] = f3;
        *(uint32_t*)(s_a + R0*AST + CL) = h2u(f0, f1);
        *(uint32_t*)(s_a + R1*AST + CL) = h2u(f2, f3);
    }
    __syncthreads();

    // ---- MLP1: wf += gelu(wf @ lw^T + lb) ----
    gemmW(ua, g_wfrag + MAT_LIN*4096, lane, wp, C);
    __syncthreads();
    FOR_FRAG {
        float b0 = __ldg(&lb[CL]), b1 = __ldg(&lb[CL+1]);
        float f0 = s_wf[R0*WST + CL]   + gelu_fast(C[mt][nt][0] + b0);
        float f1 = s_wf[R0*WST + CL+1] + gelu_fast(C[mt][nt][1] + b1);
        float f2 = s_wf[R1*WST + CL]   + gelu_fast(C[mt][nt][2] + b0);
        float f3 = s_wf[R1*WST + CL+1] + gelu_fast(C[mt][nt][3] + b1);
        s_wf[R0*WST + CL] = f0; s_wf[R0*WST + CL+1] = f1;
        s_wf[R1*WST + CL] = f2; s_wf[R1*WST + CL+1] = f3;
        *(uint32_t*)(s_a + R0*AST + CL) = h2u(f0, f1);
        *(uint32_t*)(s_a + R1*AST + CL) = h2u(f2, f3);
    }
    __syncthreads();

    // ---- self-attention projections ----
    gemmW(ua, g_wfrag + MAT_K2*4096, lane, wp, C);
    FOR_FRAG {
        *(uint32_t*)(s_b + R0*AST + CL) = h2u(C[mt][nt][0], C[mt][nt][1]);
        *(uint32_t*)(s_b + R1*AST + CL) = h2u(C[mt][nt][2], C[mt][nt][3]);
    }
    gemmW(ua, g_wfrag + MAT_V2*4096, lane, wp, C);
    FOR_FRAG {
        s_vt[(CL  )*VST + R0] = __float2half(C[mt][nt][0]);
        s_vt[(CL+1)*VST + R0] = __float2half(C[mt][nt][1]);
        s_vt[(CL  )*VST + R1] = __float2half(C[mt][nt][2]);
        s_vt[(CL+1)*VST + R1] = __float2half(C[mt][nt][3]);
    }
    gemmW(ua, g_wfrag + MAT_Q2*4096, lane, wp, C);
    __syncthreads();
    FOR_FRAG {
        *(uint32_t*)(s_a + R0*AST + CL) = h2u(C[mt][nt][0], C[mt][nt][1]);
        *(uint32_t*)(s_a + R1*AST + CL) = h2u(C[mt][nt][2], C[mt][nt][3]);
    }
    __syncthreads();

    // ---- logits2 = q2 @ k2^T ----
    gemmQK(ua, ub, lane, wp, Cq);
    #pragma unroll
    for (int mt = 0; mt < 4; mt++) {
        int cc = wp*8 + 2*t;
        s_p[(mt*16+g)*PST + cc]     = Cq[mt][0]*SCALE;
        s_p[(mt*16+g)*PST + cc+1]   = Cq[mt][1]*SCALE;
        s_p[(mt*16+g+8)*PST + cc]   = Cq[mt][2]*SCALE;
        s_p[(mt*16+g+8)*PST + cc+1] = Cq[mt][3]*SCALE;
    }
    __syncthreads();
    {
        int row = tid >> 2, q = tid & 3;
        float* pr = s_p + row*PST + q*16;
        float m = -1e30f, v[16];
        #pragma unroll
        for (int k = 0; k < 16; k++) { v[k] = pr[k]; m = fmaxf(m, v[k]); }
        m = fmaxf(m, __shfl_xor_sync(0xffffffffu, m, 1));
        m = fmaxf(m, __shfl_xor_sync(0xffffffffu, m, 2));
        float s = 0.f;
        #pragma unroll
        for (int k = 0; k < 16; k++) { v[k] = __expf(v[k] - m); s += v[k]; }
        s += __shfl_xor_sync(0xffffffffu, s, 1);
        s += __shfl_xor_sync(0xffffffffu, s, 2);
        float inv = 1.0f / s;
        #pragma unroll
        for (int u = 0; u < 8; u++)
            *(uint32_t*)(s_a + row*AST + q*16 + 2*u) = h2u(v[2*u]*inv, v[2*u+1]*inv);
    }
    __syncthreads();

    // ---- av2 = attn @ v2 -> s_b (half) ----
    gemmAV(ua, uvt, lane, wp, C);
    FOR_FRAG {
        *(uint32_t*)(s_b + R0*AST + CL) = h2u(C[mt][nt][0], C[mt][nt][1]);
        *(uint32_t*)(s_b + R1*AST + CL) = h2u(C[mt][nt][2], C[mt][nt][3]);
    }
    __syncthreads();

    // ---- scrambled residual: wf[i][j] += av[j%64][2i + j/64] ----
    #pragma unroll
    for (int k = 0; k < 32; k++) {
        int id2 = tid + 256*k;
        int i = id2 >> 7, j = id2 & 127;
        float f = s_wf[i*WST + j] + __half2float(s_b[(j & 63)*AST + 2*i + (j >> 6)]);
        s_wf[i*WST + j] = f;
        s_a[i*AST + j] = __float2half(f);
    }
    __syncthreads();

    // ---- MLP2: wf += gelu(wf @ pw^T + pb) ----
    gemmW(ua, g_wfrag + MAT_PR*4096, lane, wp, C);
    __syncthreads();
    FOR_FRAG {
        float b0 = __ldg(&pb[CL]), b1 = __ldg(&pb[CL+1]);
        s_wf[R0*WST + CL]   += gelu_fast(C[mt][nt][0] + b0);
        s_wf[R0*WST + CL+1] += gelu_fast(C[mt][nt][1] + b1);
        s_wf[R1*WST + CL]   += gelu_fast(C[mt][nt][2] + b0);
        s_wf[R1*WST + CL+1] += gelu_fast(C[mt][nt][3] + b1);
    }
    __syncthreads();

    // ---- scatter ----
    {
        int col = tid & 7, r = (tid >> 3) & 7, c0 = tid >> 6;
        int t8 = r*8 + col;
        #pragma unroll
        for (int k = 0; k < 32; k++) {
            int c = c0 + 4*k;
            obase[(size_t)c*plane + r*NW + col] = s_wf[t8*WST + c];
        }
    }
    #undef FOR_FRAG
    #undef R0
    #undef R1
    #undef CL
}

// ---------------- launch ------------------------------------------------------
extern "C" void kernel_launch(void* const* d_in, const int* in_sizes, int n_in,
                              void* d_out, int out_size) {
    const float* fm   = (const float*)d_in[0];
    const float* unc  = (const float*)d_in[1];
    const float* qgw  = (const float*)d_in[2];
    const float* kvw  = (const float*)d_in[3];
    const float* lw   = (const float*)d_in[4];
    const float* lb   = (const float*)d_in[5];
    const float* qkvw = (const float*)d_in[6];
    const float* pw   = (const float*)d_in[7];
    const float* pb   = (const float*)d_in[8];
    float* out = (float*)d_out;

    cudaFuncSetAttribute(window_kernel,
                         cudaFuncAttributeMaxDynamicSharedMemorySize, SMEMB);

    prep_kernel<<<2608, 512>>>((const float4*)fm, (float4*)out, unc,
                               qgw, lw, qkvw, pw);
    selkv_kernel<<<16, 1024>>>(kvw);
    window_kernel<<<NSEL, 256, SMEMB>>>(fm, lb, pb, out);
}

// round 15
// speedup vs baseline: 1.2293x; 1.0012x over previous
#include <cuda_runtime.h>
#include <cuda_fp16.h>
#include <math.h>
#include <stdint.h>

#define NB    2
#define NC    128
#define NH    512
#define NW    512
#define NWIN  4096
#define NWF   1228
#define NSEL  (NB*NWF)
#define SCALE 0.08838834764831845f

// ---------------- static device scratch -------------------------------------
__device__ float g_score[NB*NWIN];
__device__ int   g_sel[NB*NWF];
__device__ int   g_cnt[NB];
__device__ float g_gx[NB*NC*64];
__device__ __align__(16) uint2  g_wfrag[6*4096];        // fragment-major weights
__device__ __align__(16) __half g_k16[NB*64*128];       // cross-attn K row-major
__device__ __align__(16) __half g_v1t[NB*128*64];       // cross-attn V transposed

#define MAT_QG 0
#define MAT_LIN 1
#define MAT_Q2 2
#define MAT_K2 3
#define MAT_V2 4
#define MAT_PR 5

// ---------------- helpers ----------------------------------------------------
__device__ __forceinline__ uint32_t h2u(float a, float b) {
    __half2 h = __floats2half2_rn(a, b);
    return reinterpret_cast<uint32_t&>(h);
}
__device__ __forceinline__ void mma16(float* c, uint32_t a0, uint32_t a1,
                                      uint32_t a2, uint32_t a3,
                                      uint32_t b0, uint32_t b1) {
    asm volatile("mma.sync.aligned.m16n8k16.row.col.f32.f16.f16.f32 "
                 "{%0,%1,%2,%3}, {%4,%5,%6,%7}, {%8,%9}, {%0,%1,%2,%3};"
                 : "+f"(c[0]), "+f"(c[1]), "+f"(c[2]), "+f"(c[3])
                 : "r"(a0), "r"(a1), "r"(a2), "r"(a3), "r"(b0), "r"(b1));
}
// fp16-accumulator variant (2x rate on legacy tensor path)
__device__ __forceinline__ void mma16h(uint32_t* c, uint32_t a0, uint32_t a1,
                                       uint32_t a2, uint32_t a3,
                                       uint32_t b0, uint32_t b1) {
    asm volatile("mma.sync.aligned.m16n8k16.row.col.f16.f16.f16.f16 "
                 "{%0,%1}, {%2,%3,%4,%5}, {%6,%7}, {%0,%1};"
                 : "+r"(c[0]), "+r"(c[1])
                 : "r"(a0), "r"(a1), "r"(a2), "r"(a3), "r"(b0), "r"(b1));
}
#define LDSM4(r0, r1, r2, r3, addr) \
    asm volatile("ldmatrix.sync.aligned.m8n8.x4.shared.b16 {%0,%1,%2,%3}, [%4];" \
                 : "=r"(r0), "=r"(r1), "=r"(r2), "=r"(r3) : "r"(addr))
__device__ __forceinline__ uint32_t smem_u32(const void* p) {
    uint32_t a;
    asm("{ .reg .u64 t; cvta.to.shared.u64 t, %1; cvt.u32.u64 %0, t; }" : "=r"(a) : "l"(p));
    return a;
}
// fast GELU with HW tanh
__device__ __forceinline__ float gelu_fast(float x) {
    float u = fmaf(0.0356774081f * x, x * x, 0.7978845608f * x);
    float th;
    asm("tanh.approx.f32 %0, %1;" : "=f"(th) : "f"(u));
    return 0.5f * x * (1.0f + th);
}

// ---------------- merged prep kernel -----------------------------------------
// blocks [0,2048): copy-all + 8x8 pool ; [2048,2560): scores ; [2560,2608): wprep
__global__ void prep_kernel(const float4* __restrict__ fm4, float4* __restrict__ out4,
                            const float* __restrict__ unc,
                            const float* __restrict__ qgw, const float* __restrict__ lw,
                            const float* __restrict__ qkvw, const float* __restrict__ pw) {
    int t = threadIdx.x;
    int bid = blockIdx.x;
    if (bid < 2048) {
        __shared__ float sp[512];
        int ci = bid & 7, bc = bid >> 3;
        const float4* base = fm4  + ((size_t)bc*NH + ci*64)*(NW/4);
        float4*       ob   = out4 + ((size_t)bc*NH + ci*64)*(NW/4);
        float acc = 0.f;
        #pragma unroll 4
        for (int it = 0; it < 16; it++) {
            int i4 = it*512 + t;
            float4 v = base[i4];
            ob[i4] = v;
            acc += (v.x + v.y) + (v.z + v.w);
        }
        int cell = (t & 127) >> 4;
        int sub  = (t >> 7) * 16 + (t & 15);
        sp[cell*64 + sub] = acc;
        __syncthreads();
        int grp = t >> 6, i = t & 63;
        for (int off = 32; off >= 1; off >>= 1) {
            if (i < off) sp[grp*64 + i] += sp[grp*64 + i + off];
            __syncthreads();
        }
        if (i == 0) g_gx[bc*64 + ci*8 + grp] = sp[grp*64] * (1.0f/4096.0f);
        return;
    }
    if (bid < 2560) {
        int sb = bid - 2048;
        if (sb == 0 && t < NB) g_cnt[t] = 0;
        int gw = sb * 16 + (t >> 5);
        int lane = t & 31;
        int b = gw / NWIN, w = gw % NWIN;
        int wh = w >> 6, ww = w & 63;
        const float* base = unc + ((size_t)b*NH + wh*8)*NW + ww*8;
        int r0 = lane >> 3, c0 = lane & 7;
        double s = (double)base[r0*NW + c0] + (double)base[(r0+4)*NW + c0];
        #pragma unroll
        for (int o = 16; o; o >>= 1) s += __shfl_down_sync(0xffffffffu, s, o);
        if (lane == 0) g_score[gw] = (float)(s * (1.0/64.0));
        return;
    }
    int i = (bid - 2560) * 512 + t;                 // < 24576
    if (i >= 24576) return;
    int mat = i >> 12, r = i & 4095;
    int kb = r >> 9, n8 = (r >> 5) & 15, lane = r & 31;
    int g = lane >> 2, tt = lane & 3;
    int n = n8*8 + g, k = kb*16 + 2*tt;
    const float* W = (mat == 0) ? qgw : (mat == 1) ? lw
                   : (mat <= 4) ? qkvw + (mat - 2)*16384 : pw;
    const float* row = W + n*128;
    uint2 o;
    o.x = h2u(row[k],   row[k+1]);
    o.y = h2u(row[k+8], row[k+9]);
    g_wfrag[i] = o;
}

// ---------------- merged select + kv kernel ----------------------------------
__global__ void selkv_kernel(const float* __restrict__ kvw) {
    __shared__ float smem_buf[128*65];
    int tid = threadIdx.x;
    if (blockIdx.x < 8) {
        float* s_sc = smem_buf;
        int b = blockIdx.x >> 2, part = blockIdx.x & 3;
        const float* sc = g_score + b*NWIN;
        for (int i = tid; i < NWIN; i += 1024) s_sc[i] = sc[i];
        __syncthreads();
        int w = part*1024 + tid;
        float my = s_sc[w];
        int rank = 0;
        #pragma unroll 8
        for (int j = 0; j < NWIN; j++) {
            float v = s_sc[j];
            rank += (v > my) || (v == my && j < w);
        }
        if (rank < NWF) {
            int pos = atomicAdd(&g_cnt[b], 1);
            g_sel[b*NWF + pos] = w;
        }
        return;
    }
    int k = blockIdx.x - 8;
    int b = k >> 2, rgrp = k & 3;
    float (*sg)[65] = (float (*)[65])smem_buf;
    for (int i = tid; i < 8192; i += 1024) sg[i >> 6][i & 63] = g_gx[b*8192 + i];
    __syncthreads();
    int p = tid & 63, rsub = tid >> 6;
    #pragma unroll
    for (int u = 0; u < 4; u++) {
        int co = rgrp*64 + rsub*4 + u;
        const float* wr = kvw + (size_t)co * 128;
        float a = 0.f;
        #pragma unroll 8
        for (int cc = 0; cc < 128; cc++) a = fmaf(sg[cc][p], __ldg(&wr[cc]), a);
        if (co < 128) g_k16[(b*64 + p)*128 + co]         = __float2half(a);
        else          g_v1t[(b*128 + (co - 128))*64 + p] = __float2half(a);
    }
}

// ---------------- fused window kernel ----------------------------------------
#define AST 136
#define VST 72
#define WST 132
#define PST 68
#define OFF_WF 0
#define OFF_P  33792
#define OFF_A  51200
#define OFF_B  68608
#define OFF_VT 86016
#define SMEMB  104448

// fp32-accum: C[4][2][4] = A @ W^T
__device__ __forceinline__ void gemmW(uint32_t ua, const uint2* __restrict__ wfr,
                                      int lane, int wp, float C[4][2][4]) {
    #pragma unroll
    for (int mt = 0; mt < 4; mt++)
        #pragma unroll
        for (int nt = 0; nt < 2; nt++)
            #pragma unroll
            for (int k = 0; k < 4; k++) C[mt][nt][k] = 0.f;
    uint32_t ab = ua + (((lane & 15)*AST + ((lane & 16) >> 1)) << 1);
    #pragma unroll
    for (int kb = 0; kb < 8; kb++) {
        uint2 w0 = __ldg(&wfr[(kb*16 + 2*wp    )*32 + lane]);
        uint2 w1 = __ldg(&wfr[(kb*16 + 2*wp + 1)*32 + lane]);
        #pragma unroll
        for (int mt = 0; mt < 4; mt++) {
            uint32_t a0, a1, a2, a3;
            LDSM4(a0, a1, a2, a3, ab + mt*(AST*32) + kb*32);
            mma16(C[mt][0], a0, a1, a2, a3, w0.x, w0.y);
            mma16(C[mt][1], a0, a1, a2, a3, w1.x, w1.y);
        }
    }
}

// fp16-accum: C2[4][2][2] (packed half2) = A @ W^T
__device__ __forceinline__ void gemmWh(uint32_t ua, const uint2* __restrict__ wfr,
                                       int lane, int wp, uint32_t C2[4][2][2]) {
    #pragma unroll
    for (int mt = 0; mt < 4; mt++)
        #pragma unroll
        for (int nt = 0; nt < 2; nt++) { C2[mt][nt][0] = 0u; C2[mt][nt][1] = 0u; }
    uint32_t ab = ua + (((lane & 15)*AST + ((lane & 16) >> 1)) << 1);
    #pragma unroll
    for (int kb = 0; kb < 8; kb++) {
        uint2 w0 = __ldg(&wfr[(kb*16 + 2*wp    )*32 + lane]);
        uint2 w1 = __ldg(&wfr[(kb*16 + 2*wp + 1)*32 + lane]);
        #pragma unroll
        for (int mt = 0; mt < 4; mt++) {
            uint32_t a0, a1, a2, a3;
            LDSM4(a0, a1, a2, a3, ab + mt*(AST*32) + kb*32);
            mma16h(C2[mt][0], a0, a1, a2, a3, w0.x, w0.y);
            mma16h(C2[mt][1], a0, a1, a2, a3, w1.x, w1.y);
        }
    }
}

// Cq[4][4] = Q(ua) @ K(ub)^T, warp strip of 8 cols (fp32 accum)
__device__ __forceinline__ void gemmQK(uint32_t ua, uint32_t ub,
                                       int lane, int wp, float Cq[4][4]) {
    #pragma unroll
    for (int mt = 0; mt < 4; mt++)
        #pragma unroll
        for (int k = 0; k < 4; k++) Cq[mt][k] = 0.f;
    uint32_t ab = ua + (((lane & 15)*AST + ((lane & 16) >> 1)) << 1);
    uint32_t bb = ub + (((wp*8 + (lane & 7))*AST + (lane >> 3)*8) << 1);
    #pragma unroll
    for (int kp = 0; kp < 4; kp++) {
        uint32_t b0, b1, b2, b3;
        LDSM4(b0, b1, b2, b3, bb + kp*64);
        #pragma unroll
        for (int mt = 0; mt < 4; mt++) {
            uint32_t a0, a1, a2, a3;
            LDSM4(a0, a1, a2, a3, ab + mt*(AST*32) + kp*64);
            mma16(Cq[mt], a0, a1, a2, a3, b0, b1);
            LDSM4(a0, a1, a2, a3, ab + mt*(AST*32) + kp*64 + 32);
            mma16(Cq[mt], a0, a1, a2, a3, b2, b3);
        }
    }
}

// C[4][2][4] = attn @ V (fp32 accum)
__device__ __forceinline__ void gemmAV(uint32_t ua, uint32_t uvt,
                                       int lane, int wp, float C[4][2][4]) {
    #pragma unroll
    for (int mt = 0; mt < 4; mt++)
        #pragma unroll
        for (int nt = 0; nt < 2; nt++)
            #pragma unroll
            for (int k = 0; k < 4; k++) C[mt][nt][k] = 0.f;
    uint32_t ab = ua + (((lane & 15)*AST + ((lane & 16) >> 1)) << 1);
    uint32_t vb = uvt + (((wp*16 + (lane & 7) + ((lane & 16) >> 1))*VST + (lane & 8)) << 1);
    #pragma unroll
    for (int kb = 0; kb < 4; kb++) {
        uint32_t b0, b1, b2, b3;
        LDSM4(b0, b1, b2, b3, vb + kb*32);
        #pragma unroll
        for (int mt = 0; mt < 4; mt++) {
            uint32_t a0, a1, a2, a3;
            LDSM4(a0, a1, a2, a3, ab + mt*(AST*32) + kb*32);
            mma16(C[mt][0], a0, a1, a2, a3, b0, b1);
            mma16(C[mt][1], a0, a1, a2, a3, b2, b3);
        }
    }
}

__global__ void __launch_bounds__(256, 2) window_kernel(
    const float* __restrict__ fm,
    const float* __restrict__ lb, const float* __restrict__ pb,
    float* __restrict__ out)
{
    extern __shared__ char sm[];
    float*  s_wf = (float*) (sm + OFF_WF);
    float*  s_p  = (float*) (sm + OFF_P);
    __half* s_a  = (__half*)(sm + OFF_A);
    __half* s_b  = (__half*)(sm + OFF_B);
    __half* s_vt = (__half*)(sm + OFF_VT);
    uint32_t ua  = smem_u32(s_a);
    uint32_t ub  = smem_u32(s_b);
    uint32_t uvt = smem_u32(s_vt);

    int tid = threadIdx.x, wp = tid >> 5, lane = tid & 31;
    int g = lane >> 2, t = lane & 3;
    int idx = blockIdx.x;
    int b = idx / NWF;
    int w = g_sel[idx];
    int wh = w >> 6, ww = w & 63;
    const size_t plane = (size_t)NH * NW;
    const float* fbase = fm  + (size_t)b*NC*plane + (size_t)(wh*8)*NW + ww*8;
    float*       obase = out + (size_t)b*NC*plane + (size_t)(wh*8)*NW + ww*8;

    // gather window + stage k1 / v1t
    {
        int col = tid & 7, r = (tid >> 3) & 7, c0 = tid >> 6;
        int t8 = r*8 + col;
        #pragma unroll
        for (int k = 0; k < 32; k++) {
            int c = c0 + 4*k;
            float v = fbase[(size_t)c*plane + r*NW + col];
            s_wf[t8*WST + c] = v;
            s_a[t8*AST + c] = __float2half(v);
        }
        const uint4* kg = (const uint4*)(g_k16 + b*8192);
        const uint4* vg = (const uint4*)(g_v1t + b*8192);
        for (int i = tid; i < 1024; i += 256) {
            int row = i >> 4, c16 = i & 15;
            *(uint4*)(s_b + row*AST + c16*8) = kg[row*16 + c16];
        }
        for (int i = tid; i < 1024; i += 256) {
            int row = i >> 3, c8 = i & 7;
            *(uint4*)(s_vt + row*VST + c8*8) = vg[row*8 + c8];
        }
    }
    __syncthreads();

    float C[4][2][4];
    float Cq[4][4];
    uint32_t C2[4][2][2];

    #define FOR_FRAG for (int mt = 0; mt < 4; mt++) for (int nt = 0; nt < 2; nt++)
    #define R0 (mt*16 + g)
    #define R1 (mt*16 + g + 8)
    #define CL (wp*16 + nt*8 + 2*t)

    // ---- q1 = wf @ Wqg^T (fp16 accum, direct half2 store) ----
    gemmWh(ua, g_wfrag + MAT_QG*4096, lane, wp, C2);
    __syncthreads();
    FOR_FRAG {
        *(uint32_t*)(s_a + R0*AST + CL) = C2[mt][nt][0];
        *(uint32_t*)(s_a + R1*AST + CL) = C2[mt][nt][1];
    }
    __syncthreads();

    // ---- logits1 = q1 @ k1^T ----
    gemmQK(ua, ub, lane, wp, Cq);
    #pragma unroll
    for (int mt = 0; mt < 4; mt++) {
        int cc = wp*8 + 2*t;
        s_p[(mt*16+g)*PST + cc]     = Cq[mt][0]*SCALE;
        s_p[(mt*16+g)*PST + cc+1]   = Cq[mt][1]*SCALE;
        s_p[(mt*16+g+8)*PST + cc]   = Cq[mt][2]*SCALE;
        s_p[(mt*16+g+8)*PST + cc+1] = Cq[mt][3]*SCALE;
    }
    __syncthreads();

    // ---- softmax1 -> s_a cols 0..63 (half) ----
    {
        int row = tid >> 2, q = tid & 3;
        float* pr = s_p + row*PST + q*16;
        float m = -1e30f, v[16];
        #pragma unroll
        for (int k = 0; k < 16; k++) { v[k] = pr[k]; m = fmaxf(m, v[k]); }
        m = fmaxf(m, __shfl_xor_sync(0xffffffffu, m, 1));
        m = fmaxf(m, __shfl_xor_sync(0xffffffffu, m, 2));
        float s = 0.f;
        #pragma unroll
        for (int k = 0; k < 16; k++) { v[k] = __expf(v[k] - m); s += v[k]; }
        s += __shfl_xor_sync(0xffffffffu, s, 1);
        s += __shfl_xor_sync(0xffffffffu, s, 2);
        float inv = 1.0f / s;
        #pragma unroll
        for (int u = 0; u < 8; u++)
            *(uint32_t*)(s_a + row*AST + q*16 + 2*u) = h2u(v[2*u]*inv, v[2*u+1]*inv);
    }
    __syncthreads();

    // ---- av1 = attn @ v1 ; wf += av1 ----
    gemmAV(ua, uvt, lane, wp, C);
    __syncthreads();
    FOR_FRAG {
        float f0 = s_wf[R0*WST + CL]   + C[mt][nt][0];
        float f1 = s_wf[R0*WST + CL+1] + C[mt][nt][1];
        float f2 = s_wf[R1*WST + CL]   + C[mt][nt][2];
        float f3 = s_wf[R1*WST + CL+1] + C[mt][nt][3];
        s_wf[R0*WST + CL] = f0; s_wf[R0*WST + CL+1] = f1;
        s_wf[R1*WST + CL] = f2; s_wf[R1*WST + CL+1] = f3;
        *(uint32_t*)(s_a + R0*AST + CL) = h2u(f0, f1);
        *(uint32_t*)(s_a + R1*AST + CL) = h2u(f2, f3);
    }
    __syncthreads();

    // ---- MLP1: wf += gelu(wf @ lw^T + lb) (fp32 accum) ----
    gemmW(ua, g_wfrag + MAT_LIN*4096, lane, wp, C);
    __syncthreads();
    FOR_FRAG {
        float b0 = __ldg(&lb[CL]), b1 = __ldg(&lb[CL+1]);
        float f0 = s_wf[R0*WST + CL]   + gelu_fast(C[mt][nt][0] + b0);
        float f1 = s_wf[R0*WST + CL+1] + gelu_fast(C[mt][nt][1] + b1);
        float f2 = s_wf[R1*WST + CL]   + gelu_fast(C[mt][nt][2] + b0);
        float f3 = s_wf[R1*WST + CL+1] + gelu_fast(C[mt][nt][3] + b1);
        s_wf[R0*WST + CL] = f0; s_wf[R0*WST + CL+1] = f1;
        s_wf[R1*WST + CL] = f2; s_wf[R1*WST + CL+1] = f3;
        *(uint32_t*)(s_a + R0*AST + CL) = h2u(f0, f1);
        *(uint32_t*)(s_a + R1*AST + CL) = h2u(f2, f3);
    }
    __syncthreads();

    // ---- self-attention projections (fp16 accum) ----
    gemmWh(ua, g_wfrag + MAT_K2*4096, lane, wp, C2);        // k2 -> s_b
    FOR_FRAG {
        *(uint32_t*)(s_b + R0*AST + CL) = C2[mt][nt][0];
        *(uint32_t*)(s_b + R1*AST + CL) = C2[mt][nt][1];
    }
    gemmWh(ua, g_wfrag + MAT_V2*4096, lane, wp, C2);        // v2 -> s_vt (transposed)
    FOR_FRAG {
        __half2 h0 = *reinterpret_cast<__half2*>(&C2[mt][nt][0]);
        __half2 h1 = *reinterpret_cast<__half2*>(&C2[mt][nt][1]);
        s_vt[(CL  )*VST + R0] = h0.x;
        s_vt[(CL+1)*VST + R0] = h0.y;
        s_vt[(CL  )*VST + R1] = h1.x;
        s_vt[(CL+1)*VST + R1] = h1.y;
    }
    gemmWh(ua, g_wfrag + MAT_Q2*4096, lane, wp, C2);        // q2 -> s_a
    __syncthreads();
    FOR_FRAG {
        *(uint32_t*)(s_a + R0*AST + CL) = C2[mt][nt][0];
        *(uint32_t*)(s_a + R1*AST + CL) = C2[mt][nt][1];
    }
    __syncthreads();

    // ---- logits2 = q2 @ k2^T ----
    gemmQK(ua, ub, lane, wp, Cq);
    #pragma unroll
    for (int mt = 0; mt < 4; mt++) {
        int cc = wp*8 + 2*t;
        s_p[(mt*16+g)*PST + cc]     = Cq[mt][0]*SCALE;
        s_p[(mt*16+g)*PST + cc+1]   = Cq[mt][1]*SCALE;
        s_p[(mt*16+g+8)*PST + cc]   = Cq[mt][2]*SCALE;
        s_p[(mt*16+g+8)*PST + cc+1] = Cq[mt][3]*SCALE;
    }
    __syncthreads();
    {
        int row = tid >> 2, q = tid & 3;
        float* pr = s_p + row*PST + q*16;
        float m = -1e30f, v[16];
        #pragma unroll
        for (int k = 0; k < 16; k++) { v[k] = pr[k]; m = fmaxf(m, v[k]); }
        m = fmaxf(m, __shfl_xor_sync(0xffffffffu, m, 1));
        m = fmaxf(m, __shfl_xor_sync(0xffffffffu, m, 2));
        float s = 0.f;
        #pragma unroll
        for (int k = 0; k < 16; k++) { v[k] = __expf(v[k] - m); s += v[k]; }
        s += __shfl_xor_sync(0xffffffffu, s, 1);
        s += __shfl_xor_sync(0xffffffffu, s, 2);
        float inv = 1.0f / s;
        #pragma unroll
        for (int u = 0; u < 8; u++)
            *(uint32_t*)(s_a + row*AST + q*16 + 2*u) = h2u(v[2*u]*inv, v[2*u+1]*inv);
    }
    __syncthreads();

    // ---- av2 = attn @ v2 -> s_b (half) ----
    gemmAV(ua, uvt, lane, wp, C);
    FOR_FRAG {
        *(uint32_t*)(s_b + R0*AST + CL) = h2u(C[mt][nt][0], C[mt][nt][1]);
        *(uint32_t*)(s_b + R1*AST + CL) = h2u(C[mt][nt][2], C[mt][nt][3]);
    }
    __syncthreads();

    // ---- scrambled residual: wf[i][j] += av[j%64][2i + j/64] ----
    #pragma unroll
    for (int k = 0; k < 32; k++) {
        int id2 = tid + 256*k;
        int i = id2 >> 7, j = id2 & 127;
        float f = s_wf[i*WST + j] + __half2float(s_b[(j & 63)*AST + 2*i + (j >> 6)]);
        s_wf[i*WST + j] = f;
        s_a[i*AST + j] = __float2half(f);
    }
    __syncthreads();

    // ---- MLP2: wf += gelu(wf @ pw^T + pb) (fp32 accum) ----
    gemmW(ua, g_wfrag + MAT_PR*4096, lane, wp, C);
    __syncthreads();
    FOR_FRAG {
        float b0 = __ldg(&pb[CL]), b1 = __ldg(&pb[CL+1]);
        s_wf[R0*WST + CL]   += gelu_fast(C[mt][nt][0] + b0);
        s_wf[R0*WST + CL+1] += gelu_fast(C[mt][nt][1] + b1);
        s_wf[R1*WST + CL]   += gelu_fast(C[mt][nt][2] + b0);
        s_wf[R1*WST + CL+1] += gelu_fast(C[mt][nt][3] + b1);
    }
    __syncthreads();

    // ---- scatter ----
    {
        int col = tid & 7, r = (tid >> 3) & 7, c0 = tid >> 6;
        int t8 = r*8 + col;
        #pragma unroll
        for (int k = 0; k < 32; k++) {
            int c = c0 + 4*k;
            obase[(size_t)c*plane + r*NW + col] = s_wf[t8*WST + c];
        }
    }
    #undef FOR_FRAG
    #undef R0
    #undef R1
    #undef CL
}

// ---------------- launch ------------------------------------------------------
extern "C" void kernel_launch(void* const* d_in, const int* in_sizes, int n_in,
                              void* d_out, int out_size) {
    const float* fm   = (const float*)d_in[0];
    const float* unc  = (const float*)d_in[1];
    const float* qgw  = (const float*)d_in[2];
    const float* kvw  = (const float*)d_in[3];
    const float* lw   = (const float*)d_in[4];
    const float* lb   = (const float*)d_in[5];
    const float* qkvw = (const float*)d_in[6];
    const float* pw   = (const float*)d_in[7];
    const float* pb   = (const float*)d_in[8];
    float* out = (float*)d_out;

    cudaFuncSetAttribute(window_kernel,
                         cudaFuncAttributeMaxDynamicSharedMemorySize, SMEMB);

    prep_kernel<<<2608, 512>>>((const float4*)fm, (float4*)out, unc,
                               qgw, lw, qkvw, pw);
    selkv_kernel<<<16, 1024>>>(kvw);
    window_kernel<<<NSEL, 256, SMEMB>>>(fm, lb, pb, out);
}

// round 17
// speedup vs baseline: 1.3200x; 1.0738x over previous
#include <cuda_runtime.h>
#include <cuda_fp16.h>
#include <math.h>
#include <stdint.h>

#define NB    2
#define NC    128
#define NH    512
#define NW    512
#define NWIN  4096
#define NWF   1228
#define NSEL  (NB*NWF)
#define SCALE 0.08838834764831845f

// ---------------- static device scratch -------------------------------------
__device__ float g_score[NB*NWIN];
__device__ int   g_sel[NB*NWF];
__device__ int   g_cnt[NB];
__device__ float g_gx[NB*NC*64];
__device__ __align__(16) uint2  g_wfrag[6*4096];        // fragment-major weights
__device__ __align__(16) __half g_k16[NB*64*128];       // cross-attn K row-major
__device__ __align__(16) __half g_v1t[NB*128*64];       // cross-attn V transposed

#define MAT_QG 0
#define MAT_LIN 1
#define MAT_Q2 2
#define MAT_K2 3
#define MAT_V2 4
#define MAT_PR 5

// ---------------- helpers ----------------------------------------------------
__device__ __forceinline__ uint32_t h2u(float a, float b) {
    __half2 h = __floats2half2_rn(a, b);
    return reinterpret_cast<uint32_t&>(h);
}
__device__ __forceinline__ void mma16(float* c, uint32_t a0, uint32_t a1,
                                      uint32_t a2, uint32_t a3,
                                      uint32_t b0, uint32_t b1) {
    asm volatile("mma.sync.aligned.m16n8k16.row.col.f32.f16.f16.f32 "
                 "{%0,%1,%2,%3}, {%4,%5,%6,%7}, {%8,%9}, {%0,%1,%2,%3};"
                 : "+f"(c[0]), "+f"(c[1]), "+f"(c[2]), "+f"(c[3])
                 : "r"(a0), "r"(a1), "r"(a2), "r"(a3), "r"(b0), "r"(b1));
}
#define LDSM4(r0, r1, r2, r3, addr) \
    asm volatile("ldmatrix.sync.aligned.m8n8.x4.shared.b16 {%0,%1,%2,%3}, [%4];" \
                 : "=r"(r0), "=r"(r1), "=r"(r2), "=r"(r3) : "r"(addr))
__device__ __forceinline__ uint32_t smem_u32(const void* p) {
    uint32_t a;
    asm("{ .reg .u64 t; cvta.to.shared.u64 t, %1; cvt.u32.u64 %0, t; }" : "=r"(a) : "l"(p));
    return a;
}
__device__ __forceinline__ float gelu_fast(float x) {
    float u = fmaf(0.0356774081f * x, x * x, 0.7978845608f * x);
    float th;
    asm("tanh.approx.f32 %0, %1;" : "=f"(th) : "f"(u));
    return 0.5f * x * (1.0f + th);
}

// ---------------- merged prep kernel (unchanged from champion) ---------------
__global__ void prep_kernel(const float4* __restrict__ fm4, float4* __restrict__ out4,
                            const float* __restrict__ unc,
                            const float* __restrict__ qgw, const float* __restrict__ lw,
                            const float* __restrict__ qkvw, const float* __restrict__ pw) {
    int t = threadIdx.x;
    int bid = blockIdx.x;
    if (bid < 2048) {
        __shared__ float sp[512];
        int ci = bid & 7, bc = bid >> 3;
        const float4* base = fm4  + ((size_t)bc*NH + ci*64)*(NW/4);
        float4*       ob   = out4 + ((size_t)bc*NH + ci*64)*(NW/4);
        float acc = 0.f;
        #pragma unroll 4
        for (int it = 0; it < 16; it++) {
            int i4 = it*512 + t;
            float4 v = base[i4];
            ob[i4] = v;
            acc += (v.x + v.y) + (v.z + v.w);
        }
        int cell = (t & 127) >> 4;
        int sub  = (t >> 7) * 16 + (t & 15);
        sp[cell*64 + sub] = acc;
        __syncthreads();
        int grp = t >> 6, i = t & 63;
        for (int off = 32; off >= 1; off >>= 1) {
            if (i < off) sp[grp*64 + i] += sp[grp*64 + i + off];
            __syncthreads();
        }
        if (i == 0) g_gx[bc*64 + ci*8 + grp] = sp[grp*64] * (1.0f/4096.0f);
        return;
    }
    if (bid < 2560) {
        int sb = bid - 2048;
        if (sb == 0 && t < NB) g_cnt[t] = 0;
        int gw = sb * 16 + (t >> 5);
        int lane = t & 31;
        int b = gw / NWIN, w = gw % NWIN;
        int wh = w >> 6, ww = w & 63;
        const float* base = unc + ((size_t)b*NH + wh*8)*NW + ww*8;
        int r0 = lane >> 3, c0 = lane & 7;
        double s = (double)base[r0*NW + c0] + (double)base[(r0+4)*NW + c0];
        #pragma unroll
        for (int o = 16; o; o >>= 1) s += __shfl_down_sync(0xffffffffu, s, o);
        if (lane == 0) g_score[gw] = (float)(s * (1.0/64.0));
        return;
    }
    int i = (bid - 2560) * 512 + t;
    if (i >= 24576) return;
    int mat = i >> 12, r = i & 4095;
    int kb = r >> 9, n8 = (r >> 5) & 15, lane = r & 31;
    int g = lane >> 2, tt = lane & 3;
    int n = n8*8 + g, k = kb*16 + 2*tt;
    const float* W = (mat == 0) ? qgw : (mat == 1) ? lw
                   : (mat <= 4) ? qkvw + (mat - 2)*16384 : pw;
    const float* row = W + n*128;
    uint2 o;
    o.x = h2u(row[k],   row[k+1]);
    o.y = h2u(row[k+8], row[k+9]);
    g_wfrag[i] = o;
}

// ---------------- merged select + kv kernel (unchanged) ----------------------
__global__ void selkv_kernel(const float* __restrict__ kvw) {
    __shared__ float smem_buf[128*65];
    int tid = threadIdx.x;
    if (blockIdx.x < 8) {
        float* s_sc = smem_buf;
        int b = blockIdx.x >> 2, part = blockIdx.x & 3;
        const float* sc = g_score + b*NWIN;
        for (int i = tid; i < NWIN; i += 1024) s_sc[i] = sc[i];
        __syncthreads();
        int w = part*1024 + tid;
        float my = s_sc[w];
        int rank = 0;
        #pragma unroll 8
        for (int j = 0; j < NWIN; j++) {
            float v = s_sc[j];
            rank += (v > my) || (v == my && j < w);
        }
        if (rank < NWF) {
            int pos = atomicAdd(&g_cnt[b], 1);
            g_sel[b*NWF + pos] = w;
        }
        return;
    }
    int k = blockIdx.x - 8;
    int b = k >> 2, rgrp = k & 3;
    float (*sg)[65] = (float (*)[65])smem_buf;
    for (int i = tid; i < 8192; i += 1024) sg[i >> 6][i & 63] = g_gx[b*8192 + i];
    __syncthreads();
    int p = tid & 63, rsub = tid >> 6;
    #pragma unroll
    for (int u = 0; u < 4; u++) {
        int co = rgrp*64 + rsub*4 + u;
        const float* wr = kvw + (size_t)co * 128;
        float a = 0.f;
        #pragma unroll 8
        for (int cc = 0; cc < 128; cc++) a = fmaf(sg[cc][p], __ldg(&wr[cc]), a);
        if (co < 128) g_k16[(b*64 + p)*128 + co]         = __float2half(a);
        else          g_v1t[(b*128 + (co - 128))*64 + p] = __float2half(a);
    }
}

// ---------------- fused window kernel (fp16 master, 3 CTA/SM) ----------------
#define AST 136    // half stride (s_q, s_a, s_b)
#define VST 72     // half stride (s_vt)
#define PST 68     // float stride (s_p, aliases s_q region)
#define OFF_Q  0            // 17408 B: q/attn halves OR logits floats (s_p)
#define OFF_A  17408        // 17408 B: wf master (fp16)
#define OFF_B  34816        // 17408 B: k1/k2/av2
#define OFF_VT 52224        // 18432 B: v1t/v2t (128 rows x 72 halves)
#define SMEMB  70656

// C[4][2][4] = A(s_a) @ W^T via fragment-major weights
__device__ __forceinline__ void gemmW(uint32_t ua, const uint2* __restrict__ wfr,
                                      int lane, int wp, float C[4][2][4]) {
    #pragma unroll
    for (int mt = 0; mt < 4; mt++)
        #pragma unroll
        for (int nt = 0; nt < 2; nt++)
            #pragma unroll
            for (int k = 0; k < 4; k++) C[mt][nt][k] = 0.f;
    uint32_t ab = ua + (((lane & 15)*AST + ((lane & 16) >> 1)) << 1);
    #pragma unroll
    for (int kb = 0; kb < 8; kb++) {
        uint2 w0 = __ldg(&wfr[(kb*16 + 2*wp    )*32 + lane]);
        uint2 w1 = __ldg(&wfr[(kb*16 + 2*wp + 1)*32 + lane]);
        #pragma unroll
        for (int mt = 0; mt < 4; mt++) {
            uint32_t a0, a1, a2, a3;
            LDSM4(a0, a1, a2, a3, ab + mt*(AST*32) + kb*32);
            mma16(C[mt][0], a0, a1, a2, a3, w0.x, w0.y);
            mma16(C[mt][1], a0, a1, a2, a3, w1.x, w1.y);
        }
    }
}

// Cq[4][4] = Q(uq) @ K(ub)^T, warp strip of 8 cols
__device__ __forceinline__ void gemmQK(uint32_t uq, uint32_t ub,
                                       int lane, int wp, float Cq[4][4]) {
    #pragma unroll
    for (int mt = 0; mt < 4; mt++)
        #pragma unroll
        for (int k = 0; k < 4; k++) Cq[mt][k] = 0.f;
    uint32_t ab = uq + (((lane & 15)*AST + ((lane & 16) >> 1)) << 1);
    uint32_t bb = ub + (((wp*8 + (lane & 7))*AST + (lane >> 3)*8) << 1);
    #pragma unroll
    for (int kp = 0; kp < 4; kp++) {
        uint32_t b0, b1, b2, b3;
        LDSM4(b0, b1, b2, b3, bb + kp*64);
        #pragma unroll
        for (int mt = 0; mt < 4; mt++) {
            uint32_t a0, a1, a2, a3;
            LDSM4(a0, a1, a2, a3, ab + mt*(AST*32) + kp*64);
            mma16(Cq[mt], a0, a1, a2, a3, b0, b1);
            LDSM4(a0, a1, a2, a3, ab + mt*(AST*32) + kp*64 + 32);
            mma16(Cq[mt], a0, a1, a2, a3, b2, b3);
        }
    }
}

// C[4][2][4] = attn(uq cols 0..63) @ V(uvt transposed), K=64
__device__ __forceinline__ void gemmAV(uint32_t uq, uint32_t uvt,
                                       int lane, int wp, float C[4][2][4]) {
    #pragma unroll
    for (int mt = 0; mt < 4; mt++)
        #pragma unroll
        for (int nt = 0; nt < 2; nt++)
            #pragma unroll
            for (int k = 0; k < 4; k++) C[mt][nt][k] = 0.f;
    uint32_t ab = uq + (((lane & 15)*AST + ((lane & 16) >> 1)) << 1);
    uint32_t vb = uvt + (((wp*16 + (lane & 7) + ((lane & 16) >> 1))*VST + (lane & 8)) << 1);
    #pragma unroll
    for (int kb = 0; kb < 4; kb++) {
        uint32_t b0, b1, b2, b3;
        LDSM4(b0, b1, b2, b3, vb + kb*32);
        #pragma unroll
        for (int mt = 0; mt < 4; mt++) {
            uint32_t a0, a1, a2, a3;
            LDSM4(a0, a1, a2, a3, ab + mt*(AST*32) + kb*32);
            mma16(C[mt][0], a0, a1, a2, a3, b0, b1);
            mma16(C[mt][1], a0, a1, a2, a3, b2, b3);
        }
    }
}

__global__ void __launch_bounds__(256, 3) window_kernel(
    const float* __restrict__ fm,
    const float* __restrict__ lb, const float* __restrict__ pb,
    float* __restrict__ out)
{
    extern __shared__ char sm[];
    __half* s_q  = (__half*)(sm + OFF_Q);     // q / attn (halves)
    float*  s_p  = (float*) (sm + OFF_Q);     // logits (floats, same region)
    __half* s_a  = (__half*)(sm + OFF_A);     // wf master (fp16)
    __half* s_b  = (__half*)(sm + OFF_B);
    __half* s_vt = (__half*)(sm + OFF_VT);
    uint32_t uq  = smem_u32(s_q);
    uint32_t ua  = smem_u32(s_a);
    uint32_t ub  = smem_u32(s_b);
    uint32_t uvt = smem_u32(s_vt);

    int tid = threadIdx.x, wp = tid >> 5, lane = tid & 31;
    int g = lane >> 2, t = lane & 3;
    int idx = blockIdx.x;
    int b = idx / NWF;
    int w = g_sel[idx];
    int wh = w >> 6, ww = w & 63;
    const size_t plane = (size_t)NH * NW;
    const float* fbase = fm  + (size_t)b*NC*plane + (size_t)(wh*8)*NW + ww*8;
    float*       obase = out + (size_t)b*NC*plane + (size_t)(wh*8)*NW + ww*8;

    // gather window -> s_a (fp16 master) + stage k1 / v1t
    {
        int col = tid & 7, r = (tid >> 3) & 7, c0 = tid >> 6;
        int t8 = r*8 + col;
        #pragma unroll
        for (int k = 0; k < 32; k++) {
            int c = c0 + 4*k;
            s_a[t8*AST + c] = __float2half(fbase[(size_t)c*plane + r*NW + col]);
        }
        const uint4* kg = (const uint4*)(g_k16 + b*8192);
        const uint4* vg = (const uint4*)(g_v1t + b*8192);
        for (int i = tid; i < 1024; i += 256) {
            int row = i >> 4, c16 = i & 15;
            *(uint4*)(s_b + row*AST + c16*8) = kg[row*16 + c16];
        }
        for (int i = tid; i < 1024; i += 256) {
            int row = i >> 3, c8 = i & 7;
            *(uint4*)(s_vt + row*VST + c8*8) = vg[row*8 + c8];
        }
    }
    __syncthreads();

    float C[4][2][4];
    float Cq[4][4];

    #define FOR_FRAG for (int mt = 0; mt < 4; mt++) for (int nt = 0; nt < 2; nt++)
    #define R0 (mt*16 + g)
    #define R1 (mt*16 + g + 8)
    #define CL (wp*16 + nt*8 + 2*t)
    #define LDH2(buf, r, c) (*(uint32_t*)((buf) + (r)*AST + (c)))
    #define STH2(buf, r, c, v) (*(uint32_t*)((buf) + (r)*AST + (c)) = (v))

    // ---- q1 = wf @ Wqg^T -> s_q ----
    gemmW(ua, g_wfrag + MAT_QG*4096, lane, wp, C);
    FOR_FRAG {
        STH2(s_q, R0, CL, h2u(C[mt][nt][0], C[mt][nt][1]));
        STH2(s_q, R1, CL, h2u(C[mt][nt][2], C[mt][nt][3]));
    }
    __syncthreads();

    // ---- logits1 = q1 @ k1^T -> s_p (overwrites q1; sync first) ----
    gemmQK(uq, ub, lane, wp, Cq);
    __syncthreads();
    #pragma unroll
    for (int mt = 0; mt < 4; mt++) {
        int cc = wp*8 + 2*t;
        s_p[(mt*16+g)*PST + cc]     = Cq[mt][0]*SCALE;
        s_p[(mt*16+g)*PST + cc+1]   = Cq[mt][1]*SCALE;
        s_p[(mt*16+g+8)*PST + cc]   = Cq[mt][2]*SCALE;
        s_p[(mt*16+g+8)*PST + cc+1] = Cq[mt][3]*SCALE;
    }
    __syncthreads();

    // ---- softmax1: s_p floats -> s_q halves ----
    {
        int row = tid >> 2, q = tid & 3;
        float* pr = s_p + row*PST + q*16;
        float m = -1e30f, v[16];
        #pragma unroll
        for (int k = 0; k < 16; k++) { v[k] = pr[k]; m = fmaxf(m, v[k]); }
        m = fmaxf(m, __shfl_xor_sync(0xffffffffu, m, 1));
        m = fmaxf(m, __shfl_xor_sync(0xffffffffu, m, 2));
        float s = 0.f;
        #pragma unroll
        for (int k = 0; k < 16; k++) { v[k] = __expf(v[k] - m); s += v[k]; }
        s += __shfl_xor_sync(0xffffffffu, s, 1);
        s += __shfl_xor_sync(0xffffffffu, s, 2);
        float inv = 1.0f / s;
        #pragma unroll
        for (int u = 0; u < 8; u++)
            *(uint32_t*)(s_q + row*AST + q*16 + 2*u) = h2u(v[2*u]*inv, v[2*u+1]*inv);
    }
    __syncthreads();

    // ---- av1 = attn @ v1 ; wf += av1 (RMW fp16 master) ----
    gemmAV(uq, uvt, lane, wp, C);
    FOR_FRAG {
        __half2 w0 = *reinterpret_cast<__half2*>(&LDH2(s_a, R0, CL));
        __half2 w1 = *reinterpret_cast<__half2*>(&LDH2(s_a, R1, CL));
        STH2(s_a, R0, CL, h2u(__low2float(w0) + C[mt][nt][0], __high2float(w0) + C[mt][nt][1]));
        STH2(s_a, R1, CL, h2u(__low2float(w1) + C[mt][nt][2], __high2float(w1) + C[mt][nt][3]));
    }
    __syncthreads();

    // ---- MLP1: wf += gelu(wf @ lw^T + lb) ----
    gemmW(ua, g_wfrag + MAT_LIN*4096, lane, wp, C);
    __syncthreads();
    FOR_FRAG {
        float b0 = __ldg(&lb[CL]), b1 = __ldg(&lb[CL+1]);
        __half2 w0 = *reinterpret_cast<__half2*>(&LDH2(s_a, R0, CL));
        __half2 w1 = *reinterpret_cast<__half2*>(&LDH2(s_a, R1, CL));
        STH2(s_a, R0, CL, h2u(__low2float(w0) + gelu_fast(C[mt][nt][0] + b0),
                              __high2float(w0) + gelu_fast(C[mt][nt][1] + b1)));
        STH2(s_a, R1, CL, h2u(__low2float(w1) + gelu_fast(C[mt][nt][2] + b0),
                              __high2float(w1) + gelu_fast(C[mt][nt][3] + b1)));
    }
    __syncthreads();

    // ---- self-attention projections ----
    gemmW(ua, g_wfrag + MAT_K2*4096, lane, wp, C);   // k2 -> s_b
    FOR_FRAG {
        STH2(s_b, R0, CL, h2u(C[mt][nt][0], C[mt][nt][1]));
        STH2(s_b, R1, CL, h2u(C[mt][nt][2], C[mt][nt][3]));
    }
    gemmW(ua, g_wfrag + MAT_V2*4096, lane, wp, C);   // v2 -> s_vt (transposed)
    FOR_FRAG {
        s_vt[(CL  )*VST + R0] = __float2half(C[mt][nt][0]);
        s_vt[(CL+1)*VST + R0] = __float2half(C[mt][nt][1]);
        s_vt[(CL  )*VST + R1] = __float2half(C[mt][nt][2]);
        s_vt[(CL+1)*VST + R1] = __float2half(C[mt][nt][3]);
    }
    gemmW(ua, g_wfrag + MAT_Q2*4096, lane, wp, C);   // q2 -> s_q
    FOR_FRAG {
        STH2(s_q, R0, CL, h2u(C[mt][nt][0], C[mt][nt][1]));
        STH2(s_q, R1, CL, h2u(C[mt][nt][2], C[mt][nt][3]));
    }
    __syncthreads();

    // ---- logits2 = q2 @ k2^T -> s_p (overwrites q2; sync first) ----
    gemmQK(uq, ub, lane, wp, Cq);
    __syncthreads();
    #pragma unroll
    for (int mt = 0; mt < 4; mt++) {
        int cc = wp*8 + 2*t;
        s_p[(mt*16+g)*PST + cc]     = Cq[mt][0]*SCALE;
        s_p[(mt*16+g)*PST + cc+1]   = Cq[mt][1]*SCALE;
        s_p[(mt*16+g+8)*PST + cc]   = Cq[mt][2]*SCALE;
        s_p[(mt*16+g+8)*PST + cc+1] = Cq[mt][3]*SCALE;
    }
    __syncthreads();
    {
        int row = tid >> 2, q = tid & 3;
        float* pr = s_p + row*PST + q*16;
        float m = -1e30f, v[16];
        #pragma unroll
        for (int k = 0; k < 16; k++) { v[k] = pr[k]; m = fmaxf(m, v[k]); }
        m = fmaxf(m, __shfl_xor_sync(0xffffffffu, m, 1));
        m = fmaxf(m, __shfl_xor_sync(0xffffffffu, m, 2));
        float s = 0.f;
        #pragma unroll
        for (int k = 0; k < 16; k++) { v[k] = __expf(v[k] - m); s += v[k]; }
        s += __shfl_xor_sync(0xffffffffu, s, 1);
        s += __shfl_xor_sync(0xffffffffu, s, 2);
        float inv = 1.0f / s;
        #pragma unroll
        for (int u = 0; u < 8; u++)
            *(uint32_t*)(s_q + row*AST + q*16 + 2*u) = h2u(v[2*u]*inv, v[2*u+1]*inv);
    }
    __syncthreads();

    // ---- av2 = attn2 @ v2 -> s_b (halves) ----
    gemmAV(uq, uvt, lane, wp, C);
    __syncthreads();
    FOR_FRAG {
        STH2(s_b, R0, CL, h2u(C[mt][nt][0], C[mt][nt][1]));
        STH2(s_b, R1, CL, h2u(C[mt][nt][2], C[mt][nt][3]));
    }
    __syncthreads();

    // ---- scrambled residual: wf[i][j] += av[j%64][2i + j/64] (RMW fp16) ----
    #pragma unroll
    for (int k = 0; k < 32; k++) {
        int id2 = tid + 256*k;
        int i = id2 >> 7, j = id2 & 127;
        float f = __half2float(s_a[i*AST + j])
                + __half2float(s_b[(j & 63)*AST + 2*i + (j >> 6)]);
        s_a[i*AST + j] = __float2half(f);
    }
    __syncthreads();

    // ---- MLP2: wf += gelu(wf @ pw^T + pb) ----
    gemmW(ua, g_wfrag + MAT_PR*4096, lane, wp, C);
    __syncthreads();
    FOR_FRAG {
        float b0 = __ldg(&pb[CL]), b1 = __ldg(&pb[CL+1]);
        __half2 w0 = *reinterpret_cast<__half2*>(&LDH2(s_a, R0, CL));
        __half2 w1 = *reinterpret_cast<__half2*>(&LDH2(s_a, R1, CL));
        STH2(s_a, R0, CL, h2u(__low2float(w0) + gelu_fast(C[mt][nt][0] + b0),
                              __high2float(w0) + gelu_fast(C[mt][nt][1] + b1)));
        STH2(s_a, R1, CL, h2u(__low2float(w1) + gelu_fast(C[mt][nt][2] + b0),
                              __high2float(w1) + gelu_fast(C[mt][nt][3] + b1)));
    }
    __syncthreads();

    // ---- scatter (from fp16 master) ----
    {
        int col = tid & 7, r = (tid >> 3) & 7, c0 = tid >> 6;
        int t8 = r*8 + col;
        #pragma unroll
        for (int k = 0; k < 32; k++) {
            int c = c0 + 4*k;
            obase[(size_t)c*plane + r*NW + col] = __half2float(s_a[t8*AST + c]);
        }
    }
    #undef FOR_FRAG
    #undef R0
    #undef R1
    #undef CL
    #undef LDH2
    #undef STH2
}

// ---------------- launch ------------------------------------------------------
extern "C" void kernel_launch(void* const* d_in, const int* in_sizes, int n_in,
                              void* d_out, int out_size) {
    const float* fm   = (const float*)d_in[0];
    const float* unc  = (const float*)d_in[1];
    const float* qgw  = (const float*)d_in[2];
    const float* kvw  = (const float*)d_in[3];
    const float* lw   = (const float*)d_in[4];
    const float* lb   = (const float*)d_in[5];
    const float* qkvw = (const float*)d_in[6];
    const float* pw   = (const float*)d_in[7];
    const float* pb   = (const float*)d_in[8];
    float* out = (float*)d_out;

    cudaFuncSetAttribute(window_kernel,
                         cudaFuncAttributeMaxDynamicSharedMemorySize, SMEMB);

    prep_kernel<<<2608, 512>>>((const float4*)fm, (float4*)out, unc,
                               qgw, lw, qkvw, pw);
    selkv_kernel<<<16, 1024>>>(kvw);
    window_kernel<<<NSEL, 256, SMEMB>>>(fm, lb, pb, out);
}